// round 12
// baseline (speedup 1.0000x reference)
#include <cuda_runtime.h>
#include <stdint.h>

#define N_NODES 100000
#define N_EDGES 1200000
#define HID     64
#define TGT     32
#define NLAY    3
#define NGRAPH  500
#define OUTW    (NLAY*TGT)   // 96
#define SCAN_B  1024
#define NBLK    ((N_NODES + SCAN_B - 1)/SCAN_B)   // 98

typedef unsigned long long ull;

// ---------------------------------------------------------------- scratch
static __device__ float g_feat[N_NODES*HID];
static __device__ float g_A   [N_NODES*HID];
static __device__ float g_h   [N_NODES*HID];
static __device__ float g_gsum [NGRAPH*HID];
static __device__ float g_gvar [NGRAPH*HID];
static __device__ float g_alpha[NGRAPH*HID];
static __device__ float g_beta [NGRAPH*HID];
static __device__ float g_ypool[NGRAPH*HID];
static __device__ float g_cnt  [NGRAPH];
static __device__ int   g_deg  [N_NODES];
static __device__ int   g_off  [N_NODES+1];
static __device__ int   g_cursor[N_NODES];
static __device__ int   g_csr  [N_EDGES];
static __device__ int   g_bsum [NBLK];

// ---------------------------------------------------------------- f32x2
__device__ __forceinline__ ull dup2(float x) {
    ull r; asm("mov.b64 %0, {%1, %1};" : "=l"(r) : "f"(x)); return r;
}
__device__ __forceinline__ ull pk2(float x, float y) {
    ull r; asm("mov.b64 %0, {%1, %2};" : "=l"(r) : "f"(x), "f"(y)); return r;
}
__device__ __forceinline__ float2 up2(ull v) {
    float lo, hi; asm("mov.b64 {%0, %1}, %2;" : "=f"(lo), "=f"(hi) : "l"(v));
    return make_float2(lo, hi);
}
__device__ __forceinline__ ull ffma2(ull a, ull b, ull c) {
    ull d; asm("fma.rn.f32x2 %0, %1, %2, %3;" : "=l"(d) : "l"(a), "l"(b), "l"(c));
    return d;
}

// ---------------------------------------------------------------- setup

__global__ void k_zero_once() {
    int i = blockIdx.x*blockDim.x + threadIdx.x;
    if (i < N_NODES) g_deg[i] = 0;
    if (i < NGRAPH)  g_cnt[i] = 0.f;
    if (i < NGRAPH*HID) { g_gsum[i] = 0.f; g_gvar[i] = 0.f; }
}

// histogram of dst degrees + per-graph node counts (merged)
__global__ void k_histcnt(const int* __restrict__ dst, const int* __restrict__ gid) {
    int i = blockIdx.x*blockDim.x + threadIdx.x;
    if (i < N_EDGES) atomicAdd(&g_deg[dst[i]], 1);
    if (i < N_NODES) atomicAdd(&g_cnt[gid[i]], 1.0f);
}

// ---------------- two-level exclusive scan of degrees

__global__ __launch_bounds__(SCAN_B) void k_scan1() {
    __shared__ int wsum[32];
    int i = blockIdx.x*SCAN_B + threadIdx.x;
    int lane = threadIdx.x & 31, wid = threadIdx.x >> 5;
    int v = (i < N_NODES) ? g_deg[i] : 0;
    int s = v;
    #pragma unroll
    for (int o = 1; o < 32; o <<= 1) {
        int t = __shfl_up_sync(~0u, s, o);
        if (lane >= o) s += t;
    }
    if (lane == 31) wsum[wid] = s;
    __syncthreads();
    if (wid == 0) {
        int ws = wsum[lane];
        #pragma unroll
        for (int o = 1; o < 32; o <<= 1) {
            int t = __shfl_up_sync(~0u, ws, o);
            if (lane >= o) ws += t;
        }
        wsum[lane] = ws;
    }
    __syncthreads();
    int excl = s - v + ((wid > 0) ? wsum[wid-1] : 0);
    if (i < N_NODES) g_off[i] = excl;
    if (threadIdx.x == SCAN_B-1) g_bsum[blockIdx.x] = wsum[31];
}

__global__ __launch_bounds__(128) void k_scan2() {
    __shared__ int buf[128];
    int tid = threadIdx.x;
    int v = (tid < NBLK) ? g_bsum[tid] : 0;
    buf[tid] = v;
    __syncthreads();
    #pragma unroll
    for (int o = 1; o < 128; o <<= 1) {
        int t = (tid >= o) ? buf[tid - o] : 0;
        __syncthreads();
        buf[tid] += t;
        __syncthreads();
    }
    if (tid < NBLK) g_bsum[tid] = buf[tid] - v;
    if (tid == 127) g_off[N_NODES] = buf[127];
}

__global__ void k_scan3() {
    int i = blockIdx.x*blockDim.x + threadIdx.x;
    if (i < N_NODES) {
        int o = g_off[i] + g_bsum[i >> 10];
        g_off[i] = o;
        g_cursor[i] = o;
    }
}

__global__ void k_scatter(const int* __restrict__ src, const int* __restrict__ dst) {
    int e = blockIdx.x*blockDim.x + threadIdx.x;
    if (e < N_EDGES) {
        int p = atomicAdd(&g_cursor[dst[e]], 1);
        g_csr[p] = src[e];
    }
}

// ------------------------------------------------ aggregation (CSR gather)
// 16 lanes per node, each lane owns 4 columns (float4). Validated optimum.
__global__ __launch_bounds__(256) void k_agg(const float* __restrict__ x, int use_x,
                                             const float* __restrict__ eps, int l) {
    unsigned t = blockIdx.x*blockDim.x + threadIdx.x;
    unsigned node = t >> 4;
    if (node >= N_NODES) return;
    int j = (int)(t & 15u) << 2;
    const float* __restrict__ f = use_x ? x : g_feat;
    float sc = 1.0f + eps[l];
    float4 acc = *(const float4*)&f[(size_t)node*HID + j];
    acc.x *= sc; acc.y *= sc; acc.z *= sc; acc.w *= sc;
    int b = g_off[node], e = g_off[node+1];
    for (; b + 4 <= e; b += 4) {
        int s0 = g_csr[b], s1 = g_csr[b+1], s2 = g_csr[b+2], s3 = g_csr[b+3];
        float4 v0 = *(const float4*)&f[(size_t)s0*HID + j];
        float4 v1 = *(const float4*)&f[(size_t)s1*HID + j];
        float4 v2 = *(const float4*)&f[(size_t)s2*HID + j];
        float4 v3 = *(const float4*)&f[(size_t)s3*HID + j];
        acc.x += (v0.x + v1.x) + (v2.x + v3.x);
        acc.y += (v0.y + v1.y) + (v2.y + v3.y);
        acc.z += (v0.z + v1.z) + (v2.z + v3.z);
        acc.w += (v0.w + v1.w) + (v2.w + v3.w);
    }
    for (; b < e; b++) {
        int s = g_csr[b];
        float4 v = *(const float4*)&f[(size_t)s*HID + j];
        acc.x += v.x; acc.y += v.y; acc.z += v.z; acc.w += v.w;
    }
    *(float4*)&g_A[(size_t)node*HID + j] = acc;
}

// ============================================================ fused kernel 1
// 128 rows / 512 threads: same inner loop, 2x barrier & weight amortization.
__global__ __launch_bounds__(512) void k_conv(
    const float* __restrict__ w1, const float* __restrict__ b1,
    const float* __restrict__ w2, const float* __restrict__ b2,
    const int*   __restrict__ gid)
{
    __shared__ float W1s[4096];
    __shared__ float W2s[4096];
    __shared__ float As[128*68];
    __shared__ float b1s[64], b2s[64];
    __shared__ int   gids[128];

    const int tid  = threadIdx.x;
    const int row0 = blockIdx.x * 128;

    for (int i = tid; i < 4096; i += 512) { W1s[i] = w1[i]; W2s[i] = w2[i]; }
    if (tid < 64) { b1s[tid] = b1[tid]; b2s[tid] = b2[tid]; }
    if (tid < 128) {
        int r = row0 + tid;
        gids[tid] = (r < N_NODES) ? gid[r] : 0;
    }
    #pragma unroll
    for (int it = 0; it < 4; it++) {
        int i = it*512 + tid;
        int r = i >> 4, kk = (i & 15) << 2;
        int row = row0 + r;
        float4 v = make_float4(0.f,0.f,0.f,0.f);
        if (row < N_NODES) v = *(const float4*)&g_A[(size_t)row*64 + kk];
        *(float4*)&As[r*68 + kk] = v;
    }
    __syncthreads();

    const int cp = tid & 31;   // column pair (2cp, 2cp+1)
    const int wr = tid >> 5;   // row group 0..15 -> rows wr*8..wr*8+7
    const float* arow = &As[wr*8*68];

    ull acc[8];
    {
        ull bb = pk2(b1s[2*cp], b1s[2*cp+1]);
        #pragma unroll
        for (int r = 0; r < 8; r++) acc[r] = bb;
    }
    #pragma unroll 4
    for (int k = 0; k < 64; k += 4) {
        ull w0 = *(const ull*)&W1s[(k+0)*64 + 2*cp];
        ull w1v = *(const ull*)&W1s[(k+1)*64 + 2*cp];
        ull w2v = *(const ull*)&W1s[(k+2)*64 + 2*cp];
        ull w3v = *(const ull*)&W1s[(k+3)*64 + 2*cp];
        #pragma unroll
        for (int rr = 0; rr < 8; rr++) {
            float4 a = *(const float4*)&arow[rr*68 + k];
            acc[rr] = ffma2(dup2(a.x), w0,  acc[rr]);
            acc[rr] = ffma2(dup2(a.y), w1v, acc[rr]);
            acc[rr] = ffma2(dup2(a.z), w2v, acc[rr]);
            acc[rr] = ffma2(dup2(a.w), w3v, acc[rr]);
        }
    }
    __syncthreads();
    #pragma unroll
    for (int rr = 0; rr < 8; rr++) {
        float2 h = up2(acc[rr]);
        *(float2*)&As[(wr*8+rr)*68 + 2*cp] =
            make_float2(fmaxf(h.x, 0.f), fmaxf(h.y, 0.f));
    }
    __syncthreads();

    {
        ull bb = pk2(b2s[2*cp], b2s[2*cp+1]);
        #pragma unroll
        for (int r = 0; r < 8; r++) acc[r] = bb;
    }
    #pragma unroll 4
    for (int k = 0; k < 64; k += 4) {
        ull w0 = *(const ull*)&W2s[(k+0)*64 + 2*cp];
        ull w1v = *(const ull*)&W2s[(k+1)*64 + 2*cp];
        ull w2v = *(const ull*)&W2s[(k+2)*64 + 2*cp];
        ull w3v = *(const ull*)&W2s[(k+3)*64 + 2*cp];
        #pragma unroll
        for (int rr = 0; rr < 8; rr++) {
            float4 a = *(const float4*)&arow[rr*68 + k];
            acc[rr] = ffma2(dup2(a.x), w0,  acc[rr]);
            acc[rr] = ffma2(dup2(a.y), w1v, acc[rr]);
            acc[rr] = ffma2(dup2(a.z), w2v, acc[rr]);
            acc[rr] = ffma2(dup2(a.w), w3v, acc[rr]);
        }
    }

    // epilogue: write h, accumulate per-graph sum(h) and sum(h^2)
    float s0=0.f, s1=0.f, q0=0.f, q1=0.f;
    int cur = gids[wr*8];
    #pragma unroll
    for (int rr = 0; rr < 8; rr++) {
        int row = row0 + wr*8 + rr;
        if (row < N_NODES) {
            float2 h = up2(acc[rr]);
            *(float2*)&g_h[(size_t)row*64 + 2*cp] = h;
            int g = gids[wr*8 + rr];
            if (g != cur) {
                atomicAdd(&g_gsum[cur*64 + 2*cp],   s0);
                atomicAdd(&g_gsum[cur*64 + 2*cp+1], s1);
                atomicAdd(&g_gvar[cur*64 + 2*cp],   q0);
                atomicAdd(&g_gvar[cur*64 + 2*cp+1], q1);
                s0=s1=q0=q1=0.f; cur = g;
            }
            s0 += h.x; s1 += h.y; q0 += h.x*h.x; q1 += h.y*h.y;
        }
    }
    atomicAdd(&g_gsum[cur*64 + 2*cp],   s0);
    atomicAdd(&g_gsum[cur*64 + 2*cp+1], s1);
    atomicAdd(&g_gvar[cur*64 + 2*cp],   q0);
    atomicAdd(&g_gvar[cur*64 + 2*cp+1], q1);
}

// ------------------------------------------------ per-(graph,ch) norm coeffs
__global__ void k_stats(const float* __restrict__ gns,
                        const float* __restrict__ gnw,
                        const float* __restrict__ gnb) {
    int i = blockIdx.x*blockDim.x + threadIdx.x;
    if (i >= NGRAPH*HID) return;
    int c = i & 63, g = i >> 6;
    float n  = fmaxf(g_cnt[g], 1.f);
    float m  = g_gsum[i] / n;
    float e2 = g_gvar[i] / n;
    float s  = gns[c];
    float var = e2 - m*m*s*(2.f - s);
    float sd  = sqrtf(fmaxf(var, 0.f) + 1e-8f);
    float al  = gnw[c] / sd;
    g_alpha[i] = al;
    g_beta[i]  = gnb[c] - al*m*s;
    g_gsum[i] = 0.f;
    g_gvar[i] = 0.f;
    g_ypool[i] = 0.f;   // clean for this layer's y-pooling
}

// ============================================================ fused kernel 2
// 128 rows / 512 threads: norm+relu -> proj GEMM1 -> relu -> y pooling
__global__ __launch_bounds__(512) void k_proj(
    const float* __restrict__ pw1, const float* __restrict__ pb1,
    const int*   __restrict__ gid, int last)
{
    __shared__ float W1s[4096];
    __shared__ float As[128*68];
    __shared__ float b1s[64];
    __shared__ int   gids[128];

    const int tid  = threadIdx.x;
    const int row0 = blockIdx.x * 128;

    for (int i = tid; i < 4096; i += 512) W1s[i] = pw1[i];
    if (tid < 64) b1s[tid] = pb1[tid];
    if (tid < 128) {
        int r = row0 + tid;
        gids[tid] = (r < N_NODES) ? gid[r] : 0;
    }
    __syncthreads();

    // GraphNorm affine + relu -> As (+ g_feat for next layer unless last)
    #pragma unroll
    for (int it = 0; it < 4; it++) {
        int i = it*512 + tid;
        int r = i >> 4, kk = (i & 15) << 2;
        int row = row0 + r;
        float4 v = make_float4(0.f,0.f,0.f,0.f);
        if (row < N_NODES) {
            int g = gids[r];
            float4 h  = *(const float4*)&g_h[(size_t)row*64 + kk];
            float4 al = *(const float4*)&g_alpha[g*64 + kk];
            float4 be = *(const float4*)&g_beta[g*64 + kk];
            v.x = fmaxf(fmaf(al.x, h.x, be.x), 0.f);
            v.y = fmaxf(fmaf(al.y, h.y, be.y), 0.f);
            v.z = fmaxf(fmaf(al.z, h.z, be.z), 0.f);
            v.w = fmaxf(fmaf(al.w, h.w, be.w), 0.f);
            if (!last) *(float4*)&g_feat[(size_t)row*64 + kk] = v;
        }
        *(float4*)&As[r*68 + kk] = v;
    }
    __syncthreads();

    // GEMM1: 64x64, col-pair (2cp, 2cp+1) x 8 rows per thread
    const int cp = tid & 31;
    const int wr = tid >> 5;
    const float* arow = &As[wr*8*68];
    ull acc[8];
    {
        ull bb = pk2(b1s[2*cp], b1s[2*cp+1]);
        #pragma unroll
        for (int r = 0; r < 8; r++) acc[r] = bb;
    }
    #pragma unroll 4
    for (int k = 0; k < 64; k += 4) {
        ull w0 = *(const ull*)&W1s[(k+0)*64 + 2*cp];
        ull w1v = *(const ull*)&W1s[(k+1)*64 + 2*cp];
        ull w2v = *(const ull*)&W1s[(k+2)*64 + 2*cp];
        ull w3v = *(const ull*)&W1s[(k+3)*64 + 2*cp];
        #pragma unroll
        for (int rr = 0; rr < 8; rr++) {
            float4 a = *(const float4*)&arow[rr*68 + k];
            acc[rr] = ffma2(dup2(a.x), w0,  acc[rr]);
            acc[rr] = ffma2(dup2(a.y), w1v, acc[rr]);
            acc[rr] = ffma2(dup2(a.z), w2v, acc[rr]);
            acc[rr] = ffma2(dup2(a.w), w3v, acc[rr]);
        }
    }

    // pooling epilogue: y = relu(acc) summed per graph -> g_ypool
    float s0 = 0.f, s1 = 0.f;
    int cur = gids[wr*8];
    #pragma unroll
    for (int rr = 0; rr < 8; rr++) {
        int row = row0 + wr*8 + rr;
        if (row < N_NODES) {
            float2 p = up2(acc[rr]);
            float y0 = fmaxf(p.x, 0.f), y1 = fmaxf(p.y, 0.f);
            int g = gids[wr*8 + rr];
            if (g != cur) {
                atomicAdd(&g_ypool[cur*64 + 2*cp],   s0);
                atomicAdd(&g_ypool[cur*64 + 2*cp+1], s1);
                s0 = 0.f; s1 = 0.f; cur = g;
            }
            s0 += y0; s1 += y1;
        }
    }
    atomicAdd(&g_ypool[cur*64 + 2*cp],   s0);
    atomicAdd(&g_ypool[cur*64 + 2*cp+1], s1);
}

// out[g, l*32+c] = (ypool[g] @ pw2)[c] / max(n,1) + pb2[c] * min(n,1)
__global__ void k_out(const float* __restrict__ pw2, const float* __restrict__ pb2,
                      float* __restrict__ out, int l) {
    int i = blockIdx.x*blockDim.x + threadIdx.x;
    if (i >= NGRAPH*TGT) return;
    int g = i >> 5, c = i & 31;
    float acc = 0.f;
    #pragma unroll 8
    for (int k = 0; k < 64; k++)
        acc = fmaf(g_ypool[g*64 + k], pw2[k*32 + c], acc);
    float n = g_cnt[g];
    out[g*OUTW + l*TGT + c] = acc / fmaxf(n, 1.f) + pb2[c] * fminf(n, 1.f);
}

// ---------------------------------------------------------------- launcher

extern "C" void kernel_launch(void* const* d_in, const int* in_sizes, int n_in,
                              void* d_out, int out_size) {
    const float* x   = (const float*)d_in[0];
    const int*   src = (const int*)  d_in[1];
    const int*   dst = (const int*)  d_in[2];
    const int*   gid = (const int*)  d_in[3];
    const float* eps = (const float*)d_in[4];
    const float* cw1 = (const float*)d_in[5];
    const float* cb1 = (const float*)d_in[6];
    const float* cw2 = (const float*)d_in[7];
    const float* cb2 = (const float*)d_in[8];
    const float* gnw = (const float*)d_in[9];
    const float* gnb = (const float*)d_in[10];
    const float* gns = (const float*)d_in[11];
    const float* pw1 = (const float*)d_in[12];
    const float* pb1 = (const float*)d_in[13];
    const float* pw2 = (const float*)d_in[14];
    const float* pb2 = (const float*)d_in[15];
    float* out = (float*)d_out;

    const int EB = (N_EDGES + 255)/256;
    const int NB = (N_NODES + 255)/256;

    k_zero_once<<<NB, 256>>>();
    k_histcnt<<<EB, 256>>>(dst, gid);
    k_scan1<<<NBLK, SCAN_B>>>();
    k_scan2<<<1, 128>>>();
    k_scan3<<<NB, 256>>>();
    k_scatter<<<EB, 256>>>(src, dst);

    const int GB = (N_NODES + 127)/128;      // 128 rows per block
    const int AB = (N_NODES*16 + 255)/256;   // 16 lanes per node

    for (int l = 0; l < NLAY; l++) {
        int use_x = (l == 0) ? 1 : 0;
        int last  = (l == NLAY-1) ? 1 : 0;
        k_agg<<<AB, 256>>>(x, use_x, eps, l);
        k_conv<<<GB, 512>>>(cw1 + l*4096, cb1 + l*64,
                            cw2 + l*4096, cb2 + l*64, gid);
        k_stats<<<(NGRAPH*HID + 255)/256, 256>>>(gns + l*64, gnw + l*64, gnb + l*64);
        k_proj<<<GB, 512>>>(pw1 + l*4096, pb1 + l*64, gid, last);
        k_out<<<(NGRAPH*TGT + 255)/256, 256>>>(pw2 + l*2048, pb2 + l*32, out, l);
    }
}

// round 13
// speedup vs baseline: 1.0522x; 1.0522x over previous
#include <cuda_runtime.h>
#include <stdint.h>

#define N_NODES 100000
#define N_EDGES 1200000
#define HID     64
#define TGT     32
#define NLAY    3
#define NGRAPH  500
#define OUTW    (NLAY*TGT)   // 96
#define SCAN_B  1024
#define NBLK    ((N_NODES + SCAN_B - 1)/SCAN_B)   // 98

typedef unsigned long long ull;

// ---------------------------------------------------------------- scratch
static __device__ float g_feat[N_NODES*HID];
static __device__ float g_A   [N_NODES*HID];
static __device__ float g_h   [N_NODES*HID];
static __device__ float g_gsum [NGRAPH*HID];
static __device__ float g_gvar [NGRAPH*HID];
static __device__ float g_alpha[NGRAPH*HID];
static __device__ float g_beta [NGRAPH*HID];
static __device__ float g_ypool[NGRAPH*HID];
static __device__ float g_cnt  [NGRAPH];
static __device__ int   g_deg  [N_NODES];
static __device__ int   g_off  [N_NODES+1];
static __device__ int   g_cursor[N_NODES];
static __device__ int   g_csr  [N_EDGES];
static __device__ int   g_bsum [NBLK];

// ---------------------------------------------------------------- f32x2
__device__ __forceinline__ ull dup2(float x) {
    ull r; asm("mov.b64 %0, {%1, %1};" : "=l"(r) : "f"(x)); return r;
}
__device__ __forceinline__ ull pk2(float x, float y) {
    ull r; asm("mov.b64 %0, {%1, %2};" : "=l"(r) : "f"(x), "f"(y)); return r;
}
__device__ __forceinline__ float2 up2(ull v) {
    float lo, hi; asm("mov.b64 {%0, %1}, %2;" : "=f"(lo), "=f"(hi) : "l"(v));
    return make_float2(lo, hi);
}
__device__ __forceinline__ ull ffma2(ull a, ull b, ull c) {
    ull d; asm("fma.rn.f32x2 %0, %1, %2, %3;" : "=l"(d) : "l"(a), "l"(b), "l"(c));
    return d;
}

// ---------------------------------------------------------------- setup

__global__ void k_zero_once() {
    int i = blockIdx.x*blockDim.x + threadIdx.x;
    if (i < N_NODES) g_deg[i] = 0;
    if (i < NGRAPH)  g_cnt[i] = 0.f;
    if (i < NGRAPH*HID) { g_gsum[i] = 0.f; g_gvar[i] = 0.f; }
}

// degree histogram + per-graph node counts (merged, one launch)
__global__ void k_histcnt(const int* __restrict__ dst, const int* __restrict__ gid) {
    int i = blockIdx.x*blockDim.x + threadIdx.x;
    if (i < N_EDGES) atomicAdd(&g_deg[dst[i]], 1);
    if (i < N_NODES) atomicAdd(&g_cnt[gid[i]], 1.0f);
}

// ---------------- two-level exclusive scan of degrees

__global__ __launch_bounds__(SCAN_B) void k_scan1() {
    __shared__ int wsum[32];
    int i = blockIdx.x*SCAN_B + threadIdx.x;
    int lane = threadIdx.x & 31, wid = threadIdx.x >> 5;
    int v = (i < N_NODES) ? g_deg[i] : 0;
    int s = v;
    #pragma unroll
    for (int o = 1; o < 32; o <<= 1) {
        int t = __shfl_up_sync(~0u, s, o);
        if (lane >= o) s += t;
    }
    if (lane == 31) wsum[wid] = s;
    __syncthreads();
    if (wid == 0) {
        int ws = wsum[lane];
        #pragma unroll
        for (int o = 1; o < 32; o <<= 1) {
            int t = __shfl_up_sync(~0u, ws, o);
            if (lane >= o) ws += t;
        }
        wsum[lane] = ws;
    }
    __syncthreads();
    int excl = s - v + ((wid > 0) ? wsum[wid-1] : 0);
    if (i < N_NODES) g_off[i] = excl;
    if (threadIdx.x == SCAN_B-1) g_bsum[blockIdx.x] = wsum[31];
}

// single-warp shfl scan over NBLK=98 block totals (no __syncthreads)
__global__ __launch_bounds__(32) void k_scan2() {
    int lane = threadIdx.x;
    int carry = 0;
    #pragma unroll
    for (int base = 0; base < NBLK; base += 32) {
        int idx = base + lane;
        int v = (idx < NBLK) ? g_bsum[idx] : 0;
        int s = v;
        #pragma unroll
        for (int o = 1; o < 32; o <<= 1) {
            int t = __shfl_up_sync(~0u, s, o);
            if (lane >= o) s += t;
        }
        if (idx < NBLK) g_bsum[idx] = carry + s - v;   // exclusive prefix
        carry += __shfl_sync(~0u, s, 31);
    }
    if (lane == 31) g_off[N_NODES] = carry;
}

__global__ void k_scan3() {
    int i = blockIdx.x*blockDim.x + threadIdx.x;
    if (i < N_NODES) {
        int o = g_off[i] + g_bsum[i >> 10];
        g_off[i] = o;
        g_cursor[i] = o;
    }
}

__global__ void k_scatter(const int* __restrict__ src, const int* __restrict__ dst) {
    int e = blockIdx.x*blockDim.x + threadIdx.x;
    if (e < N_EDGES) {
        int p = atomicAdd(&g_cursor[dst[e]], 1);
        g_csr[p] = src[e];
    }
}

// ------------------------------------------------ aggregation (CSR gather)
// 16 lanes per node, each lane owns 4 columns (float4). Validated optimum.
__global__ __launch_bounds__(256) void k_agg(const float* __restrict__ x, int use_x,
                                             const float* __restrict__ eps, int l) {
    unsigned t = blockIdx.x*blockDim.x + threadIdx.x;
    unsigned node = t >> 4;
    if (node >= N_NODES) return;
    int j = (int)(t & 15u) << 2;
    const float* __restrict__ f = use_x ? x : g_feat;
    float sc = 1.0f + eps[l];
    float4 acc = *(const float4*)&f[(size_t)node*HID + j];
    acc.x *= sc; acc.y *= sc; acc.z *= sc; acc.w *= sc;
    int b = g_off[node], e = g_off[node+1];
    for (; b + 4 <= e; b += 4) {
        int s0 = g_csr[b], s1 = g_csr[b+1], s2 = g_csr[b+2], s3 = g_csr[b+3];
        float4 v0 = *(const float4*)&f[(size_t)s0*HID + j];
        float4 v1 = *(const float4*)&f[(size_t)s1*HID + j];
        float4 v2 = *(const float4*)&f[(size_t)s2*HID + j];
        float4 v3 = *(const float4*)&f[(size_t)s3*HID + j];
        acc.x += (v0.x + v1.x) + (v2.x + v3.x);
        acc.y += (v0.y + v1.y) + (v2.y + v3.y);
        acc.z += (v0.z + v1.z) + (v2.z + v3.z);
        acc.w += (v0.w + v1.w) + (v2.w + v3.w);
    }
    for (; b < e; b++) {
        int s = g_csr[b];
        float4 v = *(const float4*)&f[(size_t)s*HID + j];
        acc.x += v.x; acc.y += v.y; acc.z += v.z; acc.w += v.w;
    }
    *(float4*)&g_A[(size_t)node*HID + j] = acc;
}

// ============================================================ fused kernel 1
// MLP (2 GEMMs, col-pair x 8-row FFMA2 tile) + GraphNorm stats epilogue
__global__ __launch_bounds__(256) void k_conv(
    const float* __restrict__ w1, const float* __restrict__ b1,
    const float* __restrict__ w2, const float* __restrict__ b2,
    const int*   __restrict__ gid)
{
    __shared__ float W1s[4096];
    __shared__ float W2s[4096];
    __shared__ float As[64*68];
    __shared__ float b1s[64], b2s[64];
    __shared__ int   gids[64];

    const int tid  = threadIdx.x;
    const int row0 = blockIdx.x * 64;

    for (int i = tid; i < 4096; i += 256) { W1s[i] = w1[i]; W2s[i] = w2[i]; }
    if (tid < 64) {
        b1s[tid] = b1[tid]; b2s[tid] = b2[tid];
        int r = row0 + tid;
        gids[tid] = (r < N_NODES) ? gid[r] : 0;
    }
    #pragma unroll
    for (int it = 0; it < 4; it++) {
        int i = it*256 + tid;
        int r = i >> 4, kk = (i & 15) << 2;
        int row = row0 + r;
        float4 v = make_float4(0.f,0.f,0.f,0.f);
        if (row < N_NODES) v = *(const float4*)&g_A[(size_t)row*64 + kk];
        *(float4*)&As[r*68 + kk] = v;
    }
    __syncthreads();

    const int cp = tid & 31;   // column pair (2cp, 2cp+1)
    const int wr = tid >> 5;   // rows wr*8 .. wr*8+7
    const float* arow = &As[wr*8*68];

    ull acc[8];
    {
        ull bb = pk2(b1s[2*cp], b1s[2*cp+1]);
        #pragma unroll
        for (int r = 0; r < 8; r++) acc[r] = bb;
    }
    #pragma unroll 4
    for (int k = 0; k < 64; k += 4) {
        ull w0 = *(const ull*)&W1s[(k+0)*64 + 2*cp];
        ull w1v = *(const ull*)&W1s[(k+1)*64 + 2*cp];
        ull w2v = *(const ull*)&W1s[(k+2)*64 + 2*cp];
        ull w3v = *(const ull*)&W1s[(k+3)*64 + 2*cp];
        #pragma unroll
        for (int rr = 0; rr < 8; rr++) {
            float4 a = *(const float4*)&arow[rr*68 + k];
            acc[rr] = ffma2(dup2(a.x), w0,  acc[rr]);
            acc[rr] = ffma2(dup2(a.y), w1v, acc[rr]);
            acc[rr] = ffma2(dup2(a.z), w2v, acc[rr]);
            acc[rr] = ffma2(dup2(a.w), w3v, acc[rr]);
        }
    }
    __syncthreads();
    #pragma unroll
    for (int rr = 0; rr < 8; rr++) {
        float2 h = up2(acc[rr]);
        *(float2*)&As[(wr*8+rr)*68 + 2*cp] =
            make_float2(fmaxf(h.x, 0.f), fmaxf(h.y, 0.f));
    }
    __syncthreads();

    {
        ull bb = pk2(b2s[2*cp], b2s[2*cp+1]);
        #pragma unroll
        for (int r = 0; r < 8; r++) acc[r] = bb;
    }
    #pragma unroll 4
    for (int k = 0; k < 64; k += 4) {
        ull w0 = *(const ull*)&W2s[(k+0)*64 + 2*cp];
        ull w1v = *(const ull*)&W2s[(k+1)*64 + 2*cp];
        ull w2v = *(const ull*)&W2s[(k+2)*64 + 2*cp];
        ull w3v = *(const ull*)&W2s[(k+3)*64 + 2*cp];
        #pragma unroll
        for (int rr = 0; rr < 8; rr++) {
            float4 a = *(const float4*)&arow[rr*68 + k];
            acc[rr] = ffma2(dup2(a.x), w0,  acc[rr]);
            acc[rr] = ffma2(dup2(a.y), w1v, acc[rr]);
            acc[rr] = ffma2(dup2(a.z), w2v, acc[rr]);
            acc[rr] = ffma2(dup2(a.w), w3v, acc[rr]);
        }
    }

    // epilogue: write h, accumulate per-graph sum(h) and sum(h^2)
    float s0=0.f, s1=0.f, q0=0.f, q1=0.f;
    int cur = gids[wr*8];
    #pragma unroll
    for (int rr = 0; rr < 8; rr++) {
        int row = row0 + wr*8 + rr;
        if (row < N_NODES) {
            float2 h = up2(acc[rr]);
            *(float2*)&g_h[(size_t)row*64 + 2*cp] = h;
            int g = gids[wr*8 + rr];
            if (g != cur) {
                atomicAdd(&g_gsum[cur*64 + 2*cp],   s0);
                atomicAdd(&g_gsum[cur*64 + 2*cp+1], s1);
                atomicAdd(&g_gvar[cur*64 + 2*cp],   q0);
                atomicAdd(&g_gvar[cur*64 + 2*cp+1], q1);
                s0=s1=q0=q1=0.f; cur = g;
            }
            s0 += h.x; s1 += h.y; q0 += h.x*h.x; q1 += h.y*h.y;
        }
    }
    atomicAdd(&g_gsum[cur*64 + 2*cp],   s0);
    atomicAdd(&g_gsum[cur*64 + 2*cp+1], s1);
    atomicAdd(&g_gvar[cur*64 + 2*cp],   q0);
    atomicAdd(&g_gvar[cur*64 + 2*cp+1], q1);
}

// ------------------------------------------------ per-(graph,ch) norm coeffs
__global__ void k_stats(const float* __restrict__ gns,
                        const float* __restrict__ gnw,
                        const float* __restrict__ gnb) {
    int i = blockIdx.x*blockDim.x + threadIdx.x;
    if (i >= NGRAPH*HID) return;
    int c = i & 63, g = i >> 6;
    float n  = fmaxf(g_cnt[g], 1.f);
    float m  = g_gsum[i] / n;
    float e2 = g_gvar[i] / n;
    float s  = gns[c];
    float var = e2 - m*m*s*(2.f - s);
    float sd  = sqrtf(fmaxf(var, 0.f) + 1e-8f);
    float al  = gnw[c] / sd;
    g_alpha[i] = al;
    g_beta[i]  = gnb[c] - al*m*s;
    g_gsum[i] = 0.f;
    g_gvar[i] = 0.f;
    g_ypool[i] = 0.f;   // clean for this layer's y-pooling
}

// ============================================================ fused kernel 2
// GraphNorm affine+relu -> proj GEMM1 -> relu -> per-graph y pooling
__global__ __launch_bounds__(256) void k_proj(
    const float* __restrict__ pw1, const float* __restrict__ pb1,
    const int*   __restrict__ gid, int last)
{
    __shared__ float W1s[4096];
    __shared__ float As[64*68];
    __shared__ float b1s[64];
    __shared__ int   gids[64];

    const int tid  = threadIdx.x;
    const int row0 = blockIdx.x * 64;

    for (int i = tid; i < 4096; i += 256) W1s[i] = pw1[i];
    if (tid < 64) {
        b1s[tid] = pb1[tid];
        int r = row0 + tid;
        gids[tid] = (r < N_NODES) ? gid[r] : 0;
    }
    __syncthreads();

    // GraphNorm affine + relu -> As (+ g_feat for next layer unless last)
    #pragma unroll
    for (int it = 0; it < 4; it++) {
        int i = it*256 + tid;
        int r = i >> 4, kk = (i & 15) << 2;
        int row = row0 + r;
        float4 v = make_float4(0.f,0.f,0.f,0.f);
        if (row < N_NODES) {
            int g = gids[r];
            float4 h  = *(const float4*)&g_h[(size_t)row*64 + kk];
            float4 al = *(const float4*)&g_alpha[g*64 + kk];
            float4 be = *(const float4*)&g_beta[g*64 + kk];
            v.x = fmaxf(fmaf(al.x, h.x, be.x), 0.f);
            v.y = fmaxf(fmaf(al.y, h.y, be.y), 0.f);
            v.z = fmaxf(fmaf(al.z, h.z, be.z), 0.f);
            v.w = fmaxf(fmaf(al.w, h.w, be.w), 0.f);
            if (!last) *(float4*)&g_feat[(size_t)row*64 + kk] = v;
        }
        *(float4*)&As[r*68 + kk] = v;
    }
    __syncthreads();

    // GEMM1: 64x64, col-pair (2cp, 2cp+1) x 8 rows per thread
    const int cp = tid & 31;
    const int wr = tid >> 5;
    const float* arow = &As[wr*8*68];
    ull acc[8];
    {
        ull bb = pk2(b1s[2*cp], b1s[2*cp+1]);
        #pragma unroll
        for (int r = 0; r < 8; r++) acc[r] = bb;
    }
    #pragma unroll 4
    for (int k = 0; k < 64; k += 4) {
        ull w0 = *(const ull*)&W1s[(k+0)*64 + 2*cp];
        ull w1v = *(const ull*)&W1s[(k+1)*64 + 2*cp];
        ull w2v = *(const ull*)&W1s[(k+2)*64 + 2*cp];
        ull w3v = *(const ull*)&W1s[(k+3)*64 + 2*cp];
        #pragma unroll
        for (int rr = 0; rr < 8; rr++) {
            float4 a = *(const float4*)&arow[rr*68 + k];
            acc[rr] = ffma2(dup2(a.x), w0,  acc[rr]);
            acc[rr] = ffma2(dup2(a.y), w1v, acc[rr]);
            acc[rr] = ffma2(dup2(a.z), w2v, acc[rr]);
            acc[rr] = ffma2(dup2(a.w), w3v, acc[rr]);
        }
    }

    // pooling epilogue: y = relu(acc) summed per graph -> g_ypool
    float s0 = 0.f, s1 = 0.f;
    int cur = gids[wr*8];
    #pragma unroll
    for (int rr = 0; rr < 8; rr++) {
        int row = row0 + wr*8 + rr;
        if (row < N_NODES) {
            float2 p = up2(acc[rr]);
            float y0 = fmaxf(p.x, 0.f), y1 = fmaxf(p.y, 0.f);
            int g = gids[wr*8 + rr];
            if (g != cur) {
                atomicAdd(&g_ypool[cur*64 + 2*cp],   s0);
                atomicAdd(&g_ypool[cur*64 + 2*cp+1], s1);
                s0 = 0.f; s1 = 0.f; cur = g;
            }
            s0 += y0; s1 += y1;
        }
    }
    atomicAdd(&g_ypool[cur*64 + 2*cp],   s0);
    atomicAdd(&g_ypool[cur*64 + 2*cp+1], s1);
}

// out[g, l*32+c] = (ypool[g] @ pw2)[c] / max(n,1) + pb2[c] * min(n,1)
__global__ void k_out(const float* __restrict__ pw2, const float* __restrict__ pb2,
                      float* __restrict__ out, int l) {
    int i = blockIdx.x*blockDim.x + threadIdx.x;
    if (i >= NGRAPH*TGT) return;
    int g = i >> 5, c = i & 31;
    float acc = 0.f;
    #pragma unroll 8
    for (int k = 0; k < 64; k++)
        acc = fmaf(g_ypool[g*64 + k], pw2[k*32 + c], acc);
    float n = g_cnt[g];
    out[g*OUTW + l*TGT + c] = acc / fmaxf(n, 1.f) + pb2[c] * fminf(n, 1.f);
}

// ---------------------------------------------------------------- launcher

extern "C" void kernel_launch(void* const* d_in, const int* in_sizes, int n_in,
                              void* d_out, int out_size) {
    const float* x   = (const float*)d_in[0];
    const int*   src = (const int*)  d_in[1];
    const int*   dst = (const int*)  d_in[2];
    const int*   gid = (const int*)  d_in[3];
    const float* eps = (const float*)d_in[4];
    const float* cw1 = (const float*)d_in[5];
    const float* cb1 = (const float*)d_in[6];
    const float* cw2 = (const float*)d_in[7];
    const float* cb2 = (const float*)d_in[8];
    const float* gnw = (const float*)d_in[9];
    const float* gnb = (const float*)d_in[10];
    const float* gns = (const float*)d_in[11];
    const float* pw1 = (const float*)d_in[12];
    const float* pb1 = (const float*)d_in[13];
    const float* pw2 = (const float*)d_in[14];
    const float* pb2 = (const float*)d_in[15];
    float* out = (float*)d_out;

    const int EB = (N_EDGES + 255)/256;
    const int NB = (N_NODES + 255)/256;

    k_zero_once<<<NB, 256>>>();
    k_histcnt<<<EB, 256>>>(dst, gid);
    k_scan1<<<NBLK, SCAN_B>>>();
    k_scan2<<<1, 32>>>();
    k_scan3<<<NB, 256>>>();
    k_scatter<<<EB, 256>>>(src, dst);

    const int GB = (N_NODES + 63)/64;
    const int AB = (N_NODES*16 + 255)/256;

    for (int l = 0; l < NLAY; l++) {
        int use_x = (l == 0) ? 1 : 0;
        int last  = (l == NLAY-1) ? 1 : 0;
        k_agg<<<AB, 256>>>(x, use_x, eps, l);
        k_conv<<<GB, 256>>>(cw1 + l*4096, cb1 + l*64,
                            cw2 + l*4096, cb2 + l*64, gid);
        k_stats<<<(NGRAPH*HID + 255)/256, 256>>>(gns + l*64, gnw + l*64, gnb + l*64);
        k_proj<<<GB, 256>>>(pw1 + l*4096, pb1 + l*64, gid, last);
        k_out<<<(NGRAPH*TGT + 255)/256, 256>>>(pw2 + l*2048, pb2 + l*32, out, l);
    }
}

// round 14
// speedup vs baseline: 1.0569x; 1.0044x over previous
#include <cuda_runtime.h>
#include <stdint.h>

#define N_NODES 100000
#define N_EDGES 1200000
#define HID     64
#define TGT     32
#define NLAY    3
#define NGRAPH  500
#define OUTW    (NLAY*TGT)   // 96
#define SCAN_B  1024
#define NBLK    ((N_NODES + SCAN_B - 1)/SCAN_B)   // 98

typedef unsigned long long ull;

// ---------------------------------------------------------------- scratch
static __device__ float g_feat[N_NODES*HID];
static __device__ float g_A   [N_NODES*HID];
static __device__ float g_h   [N_NODES*HID];
static __device__ float g_gsum [NGRAPH*HID];
static __device__ float g_gvar [NGRAPH*HID];
static __device__ float g_alpha[NGRAPH*HID];
static __device__ float g_beta [NGRAPH*HID];
static __device__ float g_ypool[2][NGRAPH*HID];   // double-buffered per layer
static __device__ float g_cnt  [NGRAPH];
static __device__ int   g_deg  [N_NODES];
static __device__ int   g_off  [N_NODES+1];
static __device__ int   g_cursor[N_NODES];
static __device__ int   g_csr  [N_EDGES];
static __device__ int   g_bsum [NBLK];

// ---------------------------------------------------------------- f32x2
__device__ __forceinline__ ull dup2(float x) {
    ull r; asm("mov.b64 %0, {%1, %1};" : "=l"(r) : "f"(x)); return r;
}
__device__ __forceinline__ ull pk2(float x, float y) {
    ull r; asm("mov.b64 %0, {%1, %2};" : "=l"(r) : "f"(x), "f"(y)); return r;
}
__device__ __forceinline__ float2 up2(ull v) {
    float lo, hi; asm("mov.b64 {%0, %1}, %2;" : "=f"(lo), "=f"(hi) : "l"(v));
    return make_float2(lo, hi);
}
__device__ __forceinline__ ull ffma2(ull a, ull b, ull c) {
    ull d; asm("fma.rn.f32x2 %0, %1, %2, %3;" : "=l"(d) : "l"(a), "l"(b), "l"(c));
    return d;
}

// ---------------------------------------------------------------- setup

__global__ void k_zero_once() {
    int i = blockIdx.x*blockDim.x + threadIdx.x;
    if (i < N_NODES) g_deg[i] = 0;
    if (i < NGRAPH)  g_cnt[i] = 0.f;
    if (i < NGRAPH*HID) { g_gsum[i] = 0.f; g_gvar[i] = 0.f; }
}

// degree histogram + per-graph node counts (merged, one launch)
__global__ void k_histcnt(const int* __restrict__ dst, const int* __restrict__ gid) {
    int i = blockIdx.x*blockDim.x + threadIdx.x;
    if (i < N_EDGES) atomicAdd(&g_deg[dst[i]], 1);
    if (i < N_NODES) atomicAdd(&g_cnt[gid[i]], 1.0f);
}

// ---------------- scan of degrees (2 kernels: block-local, then fixup)

__global__ __launch_bounds__(SCAN_B) void k_scan1() {
    __shared__ int wsum[32];
    int i = blockIdx.x*SCAN_B + threadIdx.x;
    int lane = threadIdx.x & 31, wid = threadIdx.x >> 5;
    int v = (i < N_NODES) ? g_deg[i] : 0;
    int s = v;
    #pragma unroll
    for (int o = 1; o < 32; o <<= 1) {
        int t = __shfl_up_sync(~0u, s, o);
        if (lane >= o) s += t;
    }
    if (lane == 31) wsum[wid] = s;
    __syncthreads();
    if (wid == 0) {
        int ws = wsum[lane];
        #pragma unroll
        for (int o = 1; o < 32; o <<= 1) {
            int t = __shfl_up_sync(~0u, ws, o);
            if (lane >= o) ws += t;
        }
        wsum[lane] = ws;
    }
    __syncthreads();
    int excl = s - v + ((wid > 0) ? wsum[wid-1] : 0);
    if (i < N_NODES) g_off[i] = excl;
    if (threadIdx.x == SCAN_B-1) g_bsum[blockIdx.x] = wsum[31];
}

// fixup: add block prefix (computed from smem-cached g_bsum), write cursors
__global__ void k_scan3() {
    __shared__ int bs[NBLK];
    int tid = threadIdx.x;
    if (tid < NBLK) bs[tid] = g_bsum[tid];
    __syncthreads();
    int i = blockIdx.x*blockDim.x + tid;
    if (i < N_NODES) {
        int K = i >> 10;
        int pre = 0;
        for (int j = 0; j < K; j++) pre += bs[j];
        int o = g_off[i] + pre;
        g_off[i] = o;
        g_cursor[i] = o;
    }
    if (i == 0) g_off[N_NODES] = N_EDGES;   // total degree == edge count
}

__global__ void k_scatter(const int* __restrict__ src, const int* __restrict__ dst) {
    int e = blockIdx.x*blockDim.x + threadIdx.x;
    if (e < N_EDGES) {
        int p = atomicAdd(&g_cursor[dst[e]], 1);
        g_csr[p] = src[e];
    }
}

// ------------------------------------------------ aggregation (CSR gather)
// 16 lanes per node, each lane owns 4 columns (float4). Validated optimum.
__global__ __launch_bounds__(256) void k_agg(const float* __restrict__ x, int use_x,
                                             const float* __restrict__ eps, int l) {
    unsigned t = blockIdx.x*blockDim.x + threadIdx.x;
    unsigned node = t >> 4;
    if (node >= N_NODES) return;
    int j = (int)(t & 15u) << 2;
    const float* __restrict__ f = use_x ? x : g_feat;
    float sc = 1.0f + eps[l];
    float4 acc = *(const float4*)&f[(size_t)node*HID + j];
    acc.x *= sc; acc.y *= sc; acc.z *= sc; acc.w *= sc;
    int b = g_off[node], e = g_off[node+1];
    for (; b + 4 <= e; b += 4) {
        int s0 = g_csr[b], s1 = g_csr[b+1], s2 = g_csr[b+2], s3 = g_csr[b+3];
        float4 v0 = *(const float4*)&f[(size_t)s0*HID + j];
        float4 v1 = *(const float4*)&f[(size_t)s1*HID + j];
        float4 v2 = *(const float4*)&f[(size_t)s2*HID + j];
        float4 v3 = *(const float4*)&f[(size_t)s3*HID + j];
        acc.x += (v0.x + v1.x) + (v2.x + v3.x);
        acc.y += (v0.y + v1.y) + (v2.y + v3.y);
        acc.z += (v0.z + v1.z) + (v2.z + v3.z);
        acc.w += (v0.w + v1.w) + (v2.w + v3.w);
    }
    for (; b < e; b++) {
        int s = g_csr[b];
        float4 v = *(const float4*)&f[(size_t)s*HID + j];
        acc.x += v.x; acc.y += v.y; acc.z += v.z; acc.w += v.w;
    }
    *(float4*)&g_A[(size_t)node*HID + j] = acc;
}

// ============================================================ fused kernel 1
// MLP (2 GEMMs, col-pair x 8-row FFMA2 tile) + GraphNorm stats epilogue
__global__ __launch_bounds__(256) void k_conv(
    const float* __restrict__ w1, const float* __restrict__ b1,
    const float* __restrict__ w2, const float* __restrict__ b2,
    const int*   __restrict__ gid)
{
    __shared__ float W1s[4096];
    __shared__ float W2s[4096];
    __shared__ float As[64*68];
    __shared__ float b1s[64], b2s[64];
    __shared__ int   gids[64];

    const int tid  = threadIdx.x;
    const int row0 = blockIdx.x * 64;

    for (int i = tid; i < 4096; i += 256) { W1s[i] = w1[i]; W2s[i] = w2[i]; }
    if (tid < 64) {
        b1s[tid] = b1[tid]; b2s[tid] = b2[tid];
        int r = row0 + tid;
        gids[tid] = (r < N_NODES) ? gid[r] : 0;
    }
    #pragma unroll
    for (int it = 0; it < 4; it++) {
        int i = it*256 + tid;
        int r = i >> 4, kk = (i & 15) << 2;
        int row = row0 + r;
        float4 v = make_float4(0.f,0.f,0.f,0.f);
        if (row < N_NODES) v = *(const float4*)&g_A[(size_t)row*64 + kk];
        *(float4*)&As[r*68 + kk] = v;
    }
    __syncthreads();

    const int cp = tid & 31;   // column pair (2cp, 2cp+1)
    const int wr = tid >> 5;   // rows wr*8 .. wr*8+7
    const float* arow = &As[wr*8*68];

    ull acc[8];
    {
        ull bb = pk2(b1s[2*cp], b1s[2*cp+1]);
        #pragma unroll
        for (int r = 0; r < 8; r++) acc[r] = bb;
    }
    #pragma unroll 4
    for (int k = 0; k < 64; k += 4) {
        ull w0 = *(const ull*)&W1s[(k+0)*64 + 2*cp];
        ull w1v = *(const ull*)&W1s[(k+1)*64 + 2*cp];
        ull w2v = *(const ull*)&W1s[(k+2)*64 + 2*cp];
        ull w3v = *(const ull*)&W1s[(k+3)*64 + 2*cp];
        #pragma unroll
        for (int rr = 0; rr < 8; rr++) {
            float4 a = *(const float4*)&arow[rr*68 + k];
            acc[rr] = ffma2(dup2(a.x), w0,  acc[rr]);
            acc[rr] = ffma2(dup2(a.y), w1v, acc[rr]);
            acc[rr] = ffma2(dup2(a.z), w2v, acc[rr]);
            acc[rr] = ffma2(dup2(a.w), w3v, acc[rr]);
        }
    }
    __syncthreads();
    #pragma unroll
    for (int rr = 0; rr < 8; rr++) {
        float2 h = up2(acc[rr]);
        *(float2*)&As[(wr*8+rr)*68 + 2*cp] =
            make_float2(fmaxf(h.x, 0.f), fmaxf(h.y, 0.f));
    }
    __syncthreads();

    {
        ull bb = pk2(b2s[2*cp], b2s[2*cp+1]);
        #pragma unroll
        for (int r = 0; r < 8; r++) acc[r] = bb;
    }
    #pragma unroll 4
    for (int k = 0; k < 64; k += 4) {
        ull w0 = *(const ull*)&W2s[(k+0)*64 + 2*cp];
        ull w1v = *(const ull*)&W2s[(k+1)*64 + 2*cp];
        ull w2v = *(const ull*)&W2s[(k+2)*64 + 2*cp];
        ull w3v = *(const ull*)&W2s[(k+3)*64 + 2*cp];
        #pragma unroll
        for (int rr = 0; rr < 8; rr++) {
            float4 a = *(const float4*)&arow[rr*68 + k];
            acc[rr] = ffma2(dup2(a.x), w0,  acc[rr]);
            acc[rr] = ffma2(dup2(a.y), w1v, acc[rr]);
            acc[rr] = ffma2(dup2(a.z), w2v, acc[rr]);
            acc[rr] = ffma2(dup2(a.w), w3v, acc[rr]);
        }
    }

    // epilogue: write h, accumulate per-graph sum(h) and sum(h^2)
    float s0=0.f, s1=0.f, q0=0.f, q1=0.f;
    int cur = gids[wr*8];
    #pragma unroll
    for (int rr = 0; rr < 8; rr++) {
        int row = row0 + wr*8 + rr;
        if (row < N_NODES) {
            float2 h = up2(acc[rr]);
            *(float2*)&g_h[(size_t)row*64 + 2*cp] = h;
            int g = gids[wr*8 + rr];
            if (g != cur) {
                atomicAdd(&g_gsum[cur*64 + 2*cp],   s0);
                atomicAdd(&g_gsum[cur*64 + 2*cp+1], s1);
                atomicAdd(&g_gvar[cur*64 + 2*cp],   q0);
                atomicAdd(&g_gvar[cur*64 + 2*cp+1], q1);
                s0=s1=q0=q1=0.f; cur = g;
            }
            s0 += h.x; s1 += h.y; q0 += h.x*h.x; q1 += h.y*h.y;
        }
    }
    atomicAdd(&g_gsum[cur*64 + 2*cp],   s0);
    atomicAdd(&g_gsum[cur*64 + 2*cp+1], s1);
    atomicAdd(&g_gvar[cur*64 + 2*cp],   q0);
    atomicAdd(&g_gvar[cur*64 + 2*cp+1], q1);
}

// ---------------- norm coeffs for layer l + pooled output of layer l-1
// zeros ypool[l&1] (written by proj(l)); out reads ypool[(l-1)&1] - race-free.
__global__ void k_stats(const float* __restrict__ gns,
                        const float* __restrict__ gnw,
                        const float* __restrict__ gnb,
                        const float* __restrict__ pw2p,   // prev-layer proj W2
                        const float* __restrict__ pb2p,   // prev-layer proj b2
                        float* __restrict__ out, int l, int do_out) {
    int i = blockIdx.x*blockDim.x + threadIdx.x;
    if (i < NGRAPH*HID) {
        int c = i & 63, g = i >> 6;
        float n  = fmaxf(g_cnt[g], 1.f);
        float m  = g_gsum[i] / n;
        float e2 = g_gvar[i] / n;
        float s  = gns[c];
        float var = e2 - m*m*s*(2.f - s);
        float sd  = sqrtf(fmaxf(var, 0.f) + 1e-8f);
        float al  = gnw[c] / sd;
        g_alpha[i] = al;
        g_beta[i]  = gnb[c] - al*m*s;
        g_gsum[i] = 0.f;
        g_gvar[i] = 0.f;
        g_ypool[l & 1][i] = 0.f;
    }
    if (do_out && i < NGRAPH*TGT) {
        const float* yp = g_ypool[(l-1) & 1];
        int g = i >> 5, c = i & 31;
        float acc = 0.f;
        #pragma unroll 8
        for (int k = 0; k < 64; k++)
            acc = fmaf(yp[g*64 + k], pw2p[k*32 + c], acc);
        float n = g_cnt[g];
        out[g*OUTW + (l-1)*TGT + c] = acc / fmaxf(n, 1.f) + pb2p[c] * fminf(n, 1.f);
    }
}

// ============================================================ fused kernel 2
// GraphNorm affine+relu -> proj GEMM1 -> relu -> per-graph y pooling
__global__ __launch_bounds__(256) void k_proj(
    const float* __restrict__ pw1, const float* __restrict__ pb1,
    const int*   __restrict__ gid, int l, int last)
{
    __shared__ float W1s[4096];
    __shared__ float As[64*68];
    __shared__ float b1s[64];
    __shared__ int   gids[64];

    float* __restrict__ yp = g_ypool[l & 1];

    const int tid  = threadIdx.x;
    const int row0 = blockIdx.x * 64;

    for (int i = tid; i < 4096; i += 256) W1s[i] = pw1[i];
    if (tid < 64) {
        b1s[tid] = pb1[tid];
        int r = row0 + tid;
        gids[tid] = (r < N_NODES) ? gid[r] : 0;
    }
    __syncthreads();

    // GraphNorm affine + relu -> As (+ g_feat for next layer unless last)
    #pragma unroll
    for (int it = 0; it < 4; it++) {
        int i = it*256 + tid;
        int r = i >> 4, kk = (i & 15) << 2;
        int row = row0 + r;
        float4 v = make_float4(0.f,0.f,0.f,0.f);
        if (row < N_NODES) {
            int g = gids[r];
            float4 h  = *(const float4*)&g_h[(size_t)row*64 + kk];
            float4 al = *(const float4*)&g_alpha[g*64 + kk];
            float4 be = *(const float4*)&g_beta[g*64 + kk];
            v.x = fmaxf(fmaf(al.x, h.x, be.x), 0.f);
            v.y = fmaxf(fmaf(al.y, h.y, be.y), 0.f);
            v.z = fmaxf(fmaf(al.z, h.z, be.z), 0.f);
            v.w = fmaxf(fmaf(al.w, h.w, be.w), 0.f);
            if (!last) *(float4*)&g_feat[(size_t)row*64 + kk] = v;
        }
        *(float4*)&As[r*68 + kk] = v;
    }
    __syncthreads();

    // GEMM1: 64x64, col-pair (2cp, 2cp+1) x 8 rows per thread
    const int cp = tid & 31;
    const int wr = tid >> 5;
    const float* arow = &As[wr*8*68];
    ull acc[8];
    {
        ull bb = pk2(b1s[2*cp], b1s[2*cp+1]);
        #pragma unroll
        for (int r = 0; r < 8; r++) acc[r] = bb;
    }
    #pragma unroll 4
    for (int k = 0; k < 64; k += 4) {
        ull w0 = *(const ull*)&W1s[(k+0)*64 + 2*cp];
        ull w1v = *(const ull*)&W1s[(k+1)*64 + 2*cp];
        ull w2v = *(const ull*)&W1s[(k+2)*64 + 2*cp];
        ull w3v = *(const ull*)&W1s[(k+3)*64 + 2*cp];
        #pragma unroll
        for (int rr = 0; rr < 8; rr++) {
            float4 a = *(const float4*)&arow[rr*68 + k];
            acc[rr] = ffma2(dup2(a.x), w0,  acc[rr]);
            acc[rr] = ffma2(dup2(a.y), w1v, acc[rr]);
            acc[rr] = ffma2(dup2(a.z), w2v, acc[rr]);
            acc[rr] = ffma2(dup2(a.w), w3v, acc[rr]);
        }
    }

    // pooling epilogue: y = relu(acc) summed per graph -> ypool[l&1]
    float s0 = 0.f, s1 = 0.f;
    int cur = gids[wr*8];
    #pragma unroll
    for (int rr = 0; rr < 8; rr++) {
        int row = row0 + wr*8 + rr;
        if (row < N_NODES) {
            float2 p = up2(acc[rr]);
            float y0 = fmaxf(p.x, 0.f), y1 = fmaxf(p.y, 0.f);
            int g = gids[wr*8 + rr];
            if (g != cur) {
                atomicAdd(&yp[cur*64 + 2*cp],   s0);
                atomicAdd(&yp[cur*64 + 2*cp+1], s1);
                s0 = 0.f; s1 = 0.f; cur = g;
            }
            s0 += y0; s1 += y1;
        }
    }
    atomicAdd(&yp[cur*64 + 2*cp],   s0);
    atomicAdd(&yp[cur*64 + 2*cp+1], s1);
}

// final-layer pooled output (layer NLAY-1, ypool buffer (NLAY-1)&1)
__global__ void k_out(const float* __restrict__ pw2, const float* __restrict__ pb2,
                      float* __restrict__ out, int l) {
    int i = blockIdx.x*blockDim.x + threadIdx.x;
    if (i >= NGRAPH*TGT) return;
    const float* yp = g_ypool[l & 1];
    int g = i >> 5, c = i & 31;
    float acc = 0.f;
    #pragma unroll 8
    for (int k = 0; k < 64; k++)
        acc = fmaf(yp[g*64 + k], pw2[k*32 + c], acc);
    float n = g_cnt[g];
    out[g*OUTW + l*TGT + c] = acc / fmaxf(n, 1.f) + pb2[c] * fminf(n, 1.f);
}

// ---------------------------------------------------------------- launcher

extern "C" void kernel_launch(void* const* d_in, const int* in_sizes, int n_in,
                              void* d_out, int out_size) {
    const float* x   = (const float*)d_in[0];
    const int*   src = (const int*)  d_in[1];
    const int*   dst = (const int*)  d_in[2];
    const int*   gid = (const int*)  d_in[3];
    const float* eps = (const float*)d_in[4];
    const float* cw1 = (const float*)d_in[5];
    const float* cb1 = (const float*)d_in[6];
    const float* cw2 = (const float*)d_in[7];
    const float* cb2 = (const float*)d_in[8];
    const float* gnw = (const float*)d_in[9];
    const float* gnb = (const float*)d_in[10];
    const float* gns = (const float*)d_in[11];
    const float* pw1 = (const float*)d_in[12];
    const float* pb1 = (const float*)d_in[13];
    const float* pw2 = (const float*)d_in[14];
    const float* pb2 = (const float*)d_in[15];
    float* out = (float*)d_out;

    const int EB = (N_EDGES + 255)/256;
    const int NB = (N_NODES + 255)/256;

    k_zero_once<<<NB, 256>>>();
    k_histcnt<<<EB, 256>>>(dst, gid);
    k_scan1<<<NBLK, SCAN_B>>>();
    k_scan3<<<NB, 256>>>();
    k_scatter<<<EB, 256>>>(src, dst);

    const int GB = (N_NODES + 63)/64;
    const int AB = (N_NODES*16 + 255)/256;
    const int SB = (NGRAPH*HID + 255)/256;

    for (int l = 0; l < NLAY; l++) {
        int use_x = (l == 0) ? 1 : 0;
        int last  = (l == NLAY-1) ? 1 : 0;
        k_agg<<<AB, 256>>>(x, use_x, eps, l);
        k_conv<<<GB, 256>>>(cw1 + l*4096, cb1 + l*64,
                            cw2 + l*4096, cb2 + l*64, gid);
        k_stats<<<SB, 256>>>(gns + l*64, gnw + l*64, gnb + l*64,
                             pw2 + (l-1)*2048, pb2 + (l-1)*32,
                             out, l, l > 0);
        k_proj<<<GB, 256>>>(pw1 + l*4096, pb1 + l*64, gid, l, last);
    }
    k_out<<<(NGRAPH*TGT + 255)/256, 256>>>(pw2 + (NLAY-1)*2048,
                                           pb2 + (NLAY-1)*32, out, NLAY-1);
}

// round 15
// speedup vs baseline: 1.0866x; 1.0281x over previous
#include <cuda_runtime.h>
#include <stdint.h>

#define N_NODES 100000
#define N_EDGES 1200000
#define HID     64
#define TGT     32
#define NLAY    3
#define NGRAPH  500
#define OUTW    (NLAY*TGT)   // 96
#define SCAN_B  1024
#define NBLK    ((N_NODES + SCAN_B - 1)/SCAN_B)   // 98
#define MAXG    8            // fast-path max distinct graphs per 64-row block

typedef unsigned long long ull;

// ---------------------------------------------------------------- scratch
static __device__ float g_feat[N_NODES*HID];
static __device__ float g_A   [N_NODES*HID];
static __device__ float g_h   [N_NODES*HID];
static __device__ float g_gsum [NGRAPH*HID];
static __device__ float g_gvar [NGRAPH*HID];
static __device__ float g_ypool[2][NGRAPH*HID];   // double-buffered per layer
static __device__ float g_cnt  [NGRAPH];
static __device__ int   g_deg  [N_NODES];
static __device__ int   g_off  [N_NODES+1];
static __device__ int   g_cursor[N_NODES];
static __device__ int   g_csr  [N_EDGES];
static __device__ int   g_bsum [NBLK];

// ---------------------------------------------------------------- f32x2
__device__ __forceinline__ ull dup2(float x) {
    ull r; asm("mov.b64 %0, {%1, %1};" : "=l"(r) : "f"(x)); return r;
}
__device__ __forceinline__ ull pk2(float x, float y) {
    ull r; asm("mov.b64 %0, {%1, %2};" : "=l"(r) : "f"(x), "f"(y)); return r;
}
__device__ __forceinline__ float2 up2(ull v) {
    float lo, hi; asm("mov.b64 {%0, %1}, %2;" : "=f"(lo), "=f"(hi) : "l"(v));
    return make_float2(lo, hi);
}
__device__ __forceinline__ ull ffma2(ull a, ull b, ull c) {
    ull d; asm("fma.rn.f32x2 %0, %1, %2, %3;" : "=l"(d) : "l"(a), "l"(b), "l"(c));
    return d;
}

// GraphNorm coefficient math (identical to old k_stats)
__device__ __forceinline__ float2 norm_coef(int g, float s, float gw, float gb) {
    // caller passes per-channel gsum/gvar via index g (= g*64+c)
    return make_float2(0.f, 0.f); // (unused; see inline versions below)
}

// ---------------------------------------------------------------- setup

__global__ void k_zero_once() {
    int i = blockIdx.x*blockDim.x + threadIdx.x;
    if (i < N_NODES) g_deg[i] = 0;
    if (i < NGRAPH)  g_cnt[i] = 0.f;
}

// degree histogram + per-graph node counts (merged, one launch)
__global__ void k_histcnt(const int* __restrict__ dst, const int* __restrict__ gid) {
    int i = blockIdx.x*blockDim.x + threadIdx.x;
    if (i < N_EDGES) atomicAdd(&g_deg[dst[i]], 1);
    if (i < N_NODES) atomicAdd(&g_cnt[gid[i]], 1.0f);
}

// ---------------- scan of degrees (block-local, then fixup)

__global__ __launch_bounds__(SCAN_B) void k_scan1() {
    __shared__ int wsum[32];
    int i = blockIdx.x*SCAN_B + threadIdx.x;
    int lane = threadIdx.x & 31, wid = threadIdx.x >> 5;
    int v = (i < N_NODES) ? g_deg[i] : 0;
    int s = v;
    #pragma unroll
    for (int o = 1; o < 32; o <<= 1) {
        int t = __shfl_up_sync(~0u, s, o);
        if (lane >= o) s += t;
    }
    if (lane == 31) wsum[wid] = s;
    __syncthreads();
    if (wid == 0) {
        int ws = wsum[lane];
        #pragma unroll
        for (int o = 1; o < 32; o <<= 1) {
            int t = __shfl_up_sync(~0u, ws, o);
            if (lane >= o) ws += t;
        }
        wsum[lane] = ws;
    }
    __syncthreads();
    int excl = s - v + ((wid > 0) ? wsum[wid-1] : 0);
    if (i < N_NODES) g_off[i] = excl;
    if (threadIdx.x == SCAN_B-1) g_bsum[blockIdx.x] = wsum[31];
}

// fixup: add block prefix (computed from smem-cached g_bsum), write cursors
__global__ void k_scan3() {
    __shared__ int bs[NBLK];
    int tid = threadIdx.x;
    if (tid < NBLK) bs[tid] = g_bsum[tid];
    __syncthreads();
    int i = blockIdx.x*blockDim.x + tid;
    if (i < N_NODES) {
        int K = i >> 10;
        int pre = 0;
        for (int j = 0; j < K; j++) pre += bs[j];
        int o = g_off[i] + pre;
        g_off[i] = o;
        g_cursor[i] = o;
    }
    if (i == 0) g_off[N_NODES] = N_EDGES;
}

__global__ void k_scatter(const int* __restrict__ src, const int* __restrict__ dst) {
    int e = blockIdx.x*blockDim.x + threadIdx.x;
    if (e < N_EDGES) {
        int p = atomicAdd(&g_cursor[dst[e]], 1);
        g_csr[p] = src[e];
    }
}

// ------------------------------------------------ aggregation (CSR gather)
// 16 lanes per node, each lane owns 4 columns (float4). Validated optimum.
// Piggyback (first blocks): zero gsum/gvar/ypool[l&1], emit out(l-1).
__global__ __launch_bounds__(256) void k_agg(const float* __restrict__ x, int use_x,
                                             const float* __restrict__ eps, int l,
                                             const float* __restrict__ pw2p,
                                             const float* __restrict__ pb2p,
                                             float* __restrict__ out, int do_out) {
    unsigned t = blockIdx.x*blockDim.x + threadIdx.x;

    // ---- piggyback: stats-buffer zeroing + previous layer pooled output
    if (t < NGRAPH*HID) {
        g_gsum[t] = 0.f; g_gvar[t] = 0.f;
        g_ypool[l & 1][t] = 0.f;
    }
    if (do_out && t < NGRAPH*TGT) {
        const float* yp = g_ypool[(l-1) & 1];
        int g = t >> 5, c = t & 31;
        float acc = 0.f;
        #pragma unroll 8
        for (int k = 0; k < 64; k++)
            acc = fmaf(yp[g*64 + k], pw2p[k*32 + c], acc);
        float n = g_cnt[g];
        out[g*OUTW + (l-1)*TGT + c] = acc / fmaxf(n, 1.f) + pb2p[c] * fminf(n, 1.f);
    }

    // ---- gather
    unsigned node = t >> 4;
    if (node >= N_NODES) return;
    int j = (int)(t & 15u) << 2;
    const float* __restrict__ f = use_x ? x : g_feat;
    float sc = 1.0f + eps[l];
    float4 acc = *(const float4*)&f[(size_t)node*HID + j];
    acc.x *= sc; acc.y *= sc; acc.z *= sc; acc.w *= sc;
    int b = g_off[node], e = g_off[node+1];
    for (; b + 4 <= e; b += 4) {
        int s0 = g_csr[b], s1 = g_csr[b+1], s2 = g_csr[b+2], s3 = g_csr[b+3];
        float4 v0 = *(const float4*)&f[(size_t)s0*HID + j];
        float4 v1 = *(const float4*)&f[(size_t)s1*HID + j];
        float4 v2 = *(const float4*)&f[(size_t)s2*HID + j];
        float4 v3 = *(const float4*)&f[(size_t)s3*HID + j];
        acc.x += (v0.x + v1.x) + (v2.x + v3.x);
        acc.y += (v0.y + v1.y) + (v2.y + v3.y);
        acc.z += (v0.z + v1.z) + (v2.z + v3.z);
        acc.w += (v0.w + v1.w) + (v2.w + v3.w);
    }
    for (; b < e; b++) {
        int s = g_csr[b];
        float4 v = *(const float4*)&f[(size_t)s*HID + j];
        acc.x += v.x; acc.y += v.y; acc.z += v.z; acc.w += v.w;
    }
    *(float4*)&g_A[(size_t)node*HID + j] = acc;
}

// ============================================================ fused kernel 1
// MLP (2 GEMMs, col-pair x 8-row FFMA2 tile) + GraphNorm stats epilogue
__global__ __launch_bounds__(256) void k_conv(
    const float* __restrict__ w1, const float* __restrict__ b1,
    const float* __restrict__ w2, const float* __restrict__ b2,
    const int*   __restrict__ gid)
{
    __shared__ float W1s[4096];
    __shared__ float W2s[4096];
    __shared__ float As[64*68];
    __shared__ float b1s[64], b2s[64];
    __shared__ int   gids[64];

    const int tid  = threadIdx.x;
    const int row0 = blockIdx.x * 64;

    for (int i = tid; i < 4096; i += 256) { W1s[i] = w1[i]; W2s[i] = w2[i]; }
    if (tid < 64) {
        b1s[tid] = b1[tid]; b2s[tid] = b2[tid];
        int r = row0 + tid;
        gids[tid] = (r < N_NODES) ? gid[r] : 0;
    }
    #pragma unroll
    for (int it = 0; it < 4; it++) {
        int i = it*256 + tid;
        int r = i >> 4, kk = (i & 15) << 2;
        int row = row0 + r;
        float4 v = make_float4(0.f,0.f,0.f,0.f);
        if (row < N_NODES) v = *(const float4*)&g_A[(size_t)row*64 + kk];
        *(float4*)&As[r*68 + kk] = v;
    }
    __syncthreads();

    const int cp = tid & 31;
    const int wr = tid >> 5;
    const float* arow = &As[wr*8*68];

    ull acc[8];
    {
        ull bb = pk2(b1s[2*cp], b1s[2*cp+1]);
        #pragma unroll
        for (int r = 0; r < 8; r++) acc[r] = bb;
    }
    #pragma unroll 4
    for (int k = 0; k < 64; k += 4) {
        ull w0 = *(const ull*)&W1s[(k+0)*64 + 2*cp];
        ull w1v = *(const ull*)&W1s[(k+1)*64 + 2*cp];
        ull w2v = *(const ull*)&W1s[(k+2)*64 + 2*cp];
        ull w3v = *(const ull*)&W1s[(k+3)*64 + 2*cp];
        #pragma unroll
        for (int rr = 0; rr < 8; rr++) {
            float4 a = *(const float4*)&arow[rr*68 + k];
            acc[rr] = ffma2(dup2(a.x), w0,  acc[rr]);
            acc[rr] = ffma2(dup2(a.y), w1v, acc[rr]);
            acc[rr] = ffma2(dup2(a.z), w2v, acc[rr]);
            acc[rr] = ffma2(dup2(a.w), w3v, acc[rr]);
        }
    }
    __syncthreads();
    #pragma unroll
    for (int rr = 0; rr < 8; rr++) {
        float2 h = up2(acc[rr]);
        *(float2*)&As[(wr*8+rr)*68 + 2*cp] =
            make_float2(fmaxf(h.x, 0.f), fmaxf(h.y, 0.f));
    }
    __syncthreads();

    {
        ull bb = pk2(b2s[2*cp], b2s[2*cp+1]);
        #pragma unroll
        for (int r = 0; r < 8; r++) acc[r] = bb;
    }
    #pragma unroll 4
    for (int k = 0; k < 64; k += 4) {
        ull w0 = *(const ull*)&W2s[(k+0)*64 + 2*cp];
        ull w1v = *(const ull*)&W2s[(k+1)*64 + 2*cp];
        ull w2v = *(const ull*)&W2s[(k+2)*64 + 2*cp];
        ull w3v = *(const ull*)&W2s[(k+3)*64 + 2*cp];
        #pragma unroll
        for (int rr = 0; rr < 8; rr++) {
            float4 a = *(const float4*)&arow[rr*68 + k];
            acc[rr] = ffma2(dup2(a.x), w0,  acc[rr]);
            acc[rr] = ffma2(dup2(a.y), w1v, acc[rr]);
            acc[rr] = ffma2(dup2(a.z), w2v, acc[rr]);
            acc[rr] = ffma2(dup2(a.w), w3v, acc[rr]);
        }
    }

    float s0=0.f, s1=0.f, q0=0.f, q1=0.f;
    int cur = gids[wr*8];
    #pragma unroll
    for (int rr = 0; rr < 8; rr++) {
        int row = row0 + wr*8 + rr;
        if (row < N_NODES) {
            float2 h = up2(acc[rr]);
            *(float2*)&g_h[(size_t)row*64 + 2*cp] = h;
            int g = gids[wr*8 + rr];
            if (g != cur) {
                atomicAdd(&g_gsum[cur*64 + 2*cp],   s0);
                atomicAdd(&g_gsum[cur*64 + 2*cp+1], s1);
                atomicAdd(&g_gvar[cur*64 + 2*cp],   q0);
                atomicAdd(&g_gvar[cur*64 + 2*cp+1], q1);
                s0=s1=q0=q1=0.f; cur = g;
            }
            s0 += h.x; s1 += h.y; q0 += h.x*h.x; q1 += h.y*h.y;
        }
    }
    atomicAdd(&g_gsum[cur*64 + 2*cp],   s0);
    atomicAdd(&g_gsum[cur*64 + 2*cp+1], s1);
    atomicAdd(&g_gvar[cur*64 + 2*cp],   q0);
    atomicAdd(&g_gvar[cur*64 + 2*cp+1], q1);
}

// ============================================================ fused kernel 2
// inline GraphNorm coeffs -> affine+relu -> proj GEMM1 -> relu -> y pooling
__global__ __launch_bounds__(256) void k_proj(
    const float* __restrict__ pw1, const float* __restrict__ pb1,
    const float* __restrict__ gns, const float* __restrict__ gnw,
    const float* __restrict__ gnb,
    const int*   __restrict__ gid, int l, int last)
{
    __shared__ float W1s[4096];
    __shared__ float As[64*68];
    __shared__ float b1s[64], gnsS[64], gnwS[64], gnbS[64];
    __shared__ float alS[MAXG*64], beS[MAXG*64];
    __shared__ int   gids[64];

    float* __restrict__ yp = g_ypool[l & 1];

    const int tid  = threadIdx.x;
    const int row0 = blockIdx.x * 64;

    for (int i = tid; i < 4096; i += 256) W1s[i] = pw1[i];
    if (tid < 64) {
        b1s[tid]  = pb1[tid];
        gnsS[tid] = gns[tid];
        gnwS[tid] = gnw[tid];
        gnbS[tid] = gnb[tid];
        int r = row0 + tid;
        gids[tid] = gid[(r < N_NODES) ? r : (N_NODES-1)];
    }
    __syncthreads();

    // ---- per-block GraphNorm coefficients (gids sorted -> contiguous range)
    const int g0  = gids[0];
    const int ngr = gids[63] - g0 + 1;
    const bool fast = (ngr <= MAXG);
    if (fast) {
        for (int i = tid; i < ngr*64; i += 256) {
            int g = g0 + (i >> 6), c = i & 63;
            float n  = fmaxf(g_cnt[g], 1.f);
            float m  = g_gsum[g*64 + c] / n;
            float e2 = g_gvar[g*64 + c] / n;
            float s  = gnsS[c];
            float var = e2 - m*m*s*(2.f - s);
            float sd  = sqrtf(fmaxf(var, 0.f) + 1e-8f);
            float al  = gnwS[c] / sd;
            alS[i] = al;
            beS[i] = gnbS[c] - al*m*s;
        }
    }
    __syncthreads();

    // ---- GraphNorm affine + relu -> As (+ g_feat unless last layer)
    #pragma unroll
    for (int it = 0; it < 4; it++) {
        int i = it*256 + tid;
        int r = i >> 4, kk = (i & 15) << 2;
        int row = row0 + r;
        float4 v = make_float4(0.f,0.f,0.f,0.f);
        if (row < N_NODES) {
            int g = gids[r];
            float4 h = *(const float4*)&g_h[(size_t)row*64 + kk];
            float4 al, be;
            if (fast) {
                int o = (g - g0)*64 + kk;
                al = *(const float4*)&alS[o];
                be = *(const float4*)&beS[o];
            } else {
                float n = fmaxf(g_cnt[g], 1.f);
                #pragma unroll
                for (int q = 0; q < 4; q++) {
                    int c = kk + q;
                    float m  = g_gsum[g*64 + c] / n;
                    float e2 = g_gvar[g*64 + c] / n;
                    float s  = gnsS[c];
                    float var = e2 - m*m*s*(2.f - s);
                    float sd  = sqrtf(fmaxf(var, 0.f) + 1e-8f);
                    float a   = gnwS[c] / sd;
                    float bcoef = gnbS[c] - a*m*s;
                    ((float*)&al)[q] = a;
                    ((float*)&be)[q] = bcoef;
                }
            }
            v.x = fmaxf(fmaf(al.x, h.x, be.x), 0.f);
            v.y = fmaxf(fmaf(al.y, h.y, be.y), 0.f);
            v.z = fmaxf(fmaf(al.z, h.z, be.z), 0.f);
            v.w = fmaxf(fmaf(al.w, h.w, be.w), 0.f);
            if (!last) *(float4*)&g_feat[(size_t)row*64 + kk] = v;
        }
        *(float4*)&As[r*68 + kk] = v;
    }
    __syncthreads();

    // ---- GEMM1: 64x64, col-pair (2cp, 2cp+1) x 8 rows per thread
    const int cp = tid & 31;
    const int wr = tid >> 5;
    const float* arow = &As[wr*8*68];
    ull acc[8];
    {
        ull bb = pk2(b1s[2*cp], b1s[2*cp+1]);
        #pragma unroll
        for (int r = 0; r < 8; r++) acc[r] = bb;
    }
    #pragma unroll 4
    for (int k = 0; k < 64; k += 4) {
        ull w0 = *(const ull*)&W1s[(k+0)*64 + 2*cp];
        ull w1v = *(const ull*)&W1s[(k+1)*64 + 2*cp];
        ull w2v = *(const ull*)&W1s[(k+2)*64 + 2*cp];
        ull w3v = *(const ull*)&W1s[(k+3)*64 + 2*cp];
        #pragma unroll
        for (int rr = 0; rr < 8; rr++) {
            float4 a = *(const float4*)&arow[rr*68 + k];
            acc[rr] = ffma2(dup2(a.x), w0,  acc[rr]);
            acc[rr] = ffma2(dup2(a.y), w1v, acc[rr]);
            acc[rr] = ffma2(dup2(a.z), w2v, acc[rr]);
            acc[rr] = ffma2(dup2(a.w), w3v, acc[rr]);
        }
    }

    // ---- pooling epilogue: y = relu(acc) summed per graph -> ypool[l&1]
    float s0 = 0.f, s1 = 0.f;
    int cur = gids[wr*8];
    #pragma unroll
    for (int rr = 0; rr < 8; rr++) {
        int row = row0 + wr*8 + rr;
        if (row < N_NODES) {
            float2 p = up2(acc[rr]);
            float y0 = fmaxf(p.x, 0.f), y1 = fmaxf(p.y, 0.f);
            int g = gids[wr*8 + rr];
            if (g != cur) {
                atomicAdd(&yp[cur*64 + 2*cp],   s0);
                atomicAdd(&yp[cur*64 + 2*cp+1], s1);
                s0 = 0.f; s1 = 0.f; cur = g;
            }
            s0 += y0; s1 += y1;
        }
    }
    atomicAdd(&yp[cur*64 + 2*cp],   s0);
    atomicAdd(&yp[cur*64 + 2*cp+1], s1);
}

// final-layer pooled output
__global__ void k_out(const float* __restrict__ pw2, const float* __restrict__ pb2,
                      float* __restrict__ out, int l) {
    int i = blockIdx.x*blockDim.x + threadIdx.x;
    if (i >= NGRAPH*TGT) return;
    const float* yp = g_ypool[l & 1];
    int g = i >> 5, c = i & 31;
    float acc = 0.f;
    #pragma unroll 8
    for (int k = 0; k < 64; k++)
        acc = fmaf(yp[g*64 + k], pw2[k*32 + c], acc);
    float n = g_cnt[g];
    out[g*OUTW + l*TGT + c] = acc / fmaxf(n, 1.f) + pb2[c] * fminf(n, 1.f);
}

// ---------------------------------------------------------------- launcher

extern "C" void kernel_launch(void* const* d_in, const int* in_sizes, int n_in,
                              void* d_out, int out_size) {
    const float* x   = (const float*)d_in[0];
    const int*   src = (const int*)  d_in[1];
    const int*   dst = (const int*)  d_in[2];
    const int*   gid = (const int*)  d_in[3];
    const float* eps = (const float*)d_in[4];
    const float* cw1 = (const float*)d_in[5];
    const float* cb1 = (const float*)d_in[6];
    const float* cw2 = (const float*)d_in[7];
    const float* cb2 = (const float*)d_in[8];
    const float* gnw = (const float*)d_in[9];
    const float* gnb = (const float*)d_in[10];
    const float* gns = (const float*)d_in[11];
    const float* pw1 = (const float*)d_in[12];
    const float* pb1 = (const float*)d_in[13];
    const float* pw2 = (const float*)d_in[14];
    const float* pb2 = (const float*)d_in[15];
    float* out = (float*)d_out;

    const int EB = (N_EDGES + 255)/256;
    const int NB = (N_NODES + 255)/256;

    k_zero_once<<<NB, 256>>>();
    k_histcnt<<<EB, 256>>>(dst, gid);
    k_scan1<<<NBLK, SCAN_B>>>();
    k_scan3<<<NB, 256>>>();
    k_scatter<<<EB, 256>>>(src, dst);

    const int GB = (N_NODES + 63)/64;
    const int AB = (N_NODES*16 + 255)/256;

    for (int l = 0; l < NLAY; l++) {
        int use_x = (l == 0) ? 1 : 0;
        int last  = (l == NLAY-1) ? 1 : 0;
        k_agg<<<AB, 256>>>(x, use_x, eps, l,
                           pw2 + (l-1)*2048, pb2 + (l-1)*32, out, l > 0);
        k_conv<<<GB, 256>>>(cw1 + l*4096, cb1 + l*64,
                            cw2 + l*4096, cb2 + l*64, gid);
        k_proj<<<GB, 256>>>(pw1 + l*4096, pb1 + l*64,
                            gns + l*64, gnw + l*64, gnb + l*64,
                            gid, l, last);
    }
    k_out<<<(NGRAPH*TGT + 255)/256, 256>>>(pw2 + (NLAY-1)*2048,
                                           pb2 + (NLAY-1)*32, out, NLAY-1);
}

// round 16
// speedup vs baseline: 1.0915x; 1.0045x over previous
#include <cuda_runtime.h>
#include <stdint.h>

#define N_NODES 100000
#define N_EDGES 1200000
#define HID     64
#define TGT     32
#define NLAY    3
#define NGRAPH  500
#define OUTW    (NLAY*TGT)   // 96
#define SCAN_B  1024
#define NBLK    ((N_NODES + SCAN_B - 1)/SCAN_B)   // 98
#define MAXG    8            // fast-path max distinct graphs per 64-row block

typedef unsigned long long ull;

// ---------------------------------------------------------------- scratch
// NOTE: __device__ globals are zero-initialized at module load; the pipeline
// is self-restoring (scan3 re-zeros g_deg, k_out re-zeros g_cnt), so no
// separate zeroing kernel is needed.
static __device__ float g_feat[N_NODES*HID];
static __device__ float g_A   [N_NODES*HID];
static __device__ float g_h   [N_NODES*HID];
static __device__ float g_gsum [NGRAPH*HID];
static __device__ float g_gvar [NGRAPH*HID];
static __device__ float g_ypool[2][NGRAPH*HID];   // double-buffered per layer
static __device__ float g_cnt  [NGRAPH];
static __device__ int   g_deg  [N_NODES];
static __device__ int   g_off  [N_NODES+1];
static __device__ int   g_cursor[N_NODES];
static __device__ int   g_csr  [N_EDGES];
static __device__ int   g_bsum [NBLK];

// ---------------------------------------------------------------- f32x2
__device__ __forceinline__ ull dup2(float x) {
    ull r; asm("mov.b64 %0, {%1, %1};" : "=l"(r) : "f"(x)); return r;
}
__device__ __forceinline__ ull pk2(float x, float y) {
    ull r; asm("mov.b64 %0, {%1, %2};" : "=l"(r) : "f"(x), "f"(y)); return r;
}
__device__ __forceinline__ float2 up2(ull v) {
    float lo, hi; asm("mov.b64 {%0, %1}, %2;" : "=f"(lo), "=f"(hi) : "l"(v));
    return make_float2(lo, hi);
}
__device__ __forceinline__ ull ffma2(ull a, ull b, ull c) {
    ull d; asm("fma.rn.f32x2 %0, %1, %2, %3;" : "=l"(d) : "l"(a), "l"(b), "l"(c));
    return d;
}

// ---------------------------------------------------------------- setup

// degree histogram + per-graph node counts (merged, one launch)
// relies on g_deg == 0 and g_cnt == 0 at entry (static init / self-restore)
__global__ void k_histcnt(const int* __restrict__ dst, const int* __restrict__ gid) {
    int i = blockIdx.x*blockDim.x + threadIdx.x;
    if (i < N_EDGES) atomicAdd(&g_deg[dst[i]], 1);
    if (i < N_NODES) atomicAdd(&g_cnt[gid[i]], 1.0f);
}

// ---------------- scan of degrees (block-local, then fixup)

__global__ __launch_bounds__(SCAN_B) void k_scan1() {
    __shared__ int wsum[32];
    int i = blockIdx.x*SCAN_B + threadIdx.x;
    int lane = threadIdx.x & 31, wid = threadIdx.x >> 5;
    int v = (i < N_NODES) ? g_deg[i] : 0;
    int s = v;
    #pragma unroll
    for (int o = 1; o < 32; o <<= 1) {
        int t = __shfl_up_sync(~0u, s, o);
        if (lane >= o) s += t;
    }
    if (lane == 31) wsum[wid] = s;
    __syncthreads();
    if (wid == 0) {
        int ws = wsum[lane];
        #pragma unroll
        for (int o = 1; o < 32; o <<= 1) {
            int t = __shfl_up_sync(~0u, ws, o);
            if (lane >= o) ws += t;
        }
        wsum[lane] = ws;
    }
    __syncthreads();
    int excl = s - v + ((wid > 0) ? wsum[wid-1] : 0);
    if (i < N_NODES) g_off[i] = excl;
    if (threadIdx.x == SCAN_B-1) g_bsum[blockIdx.x] = wsum[31];
}

// fixup: warp-scan block totals into exclusive prefix (smem), add, cursors.
// Also re-zeros g_deg for the next replay (last reader was k_scan1).
__global__ void k_scan3() {
    __shared__ int bs[NBLK];
    int tid = threadIdx.x;
    if (tid < NBLK) bs[tid] = g_bsum[tid];
    __syncthreads();
    if (tid < 32) {
        int lane = tid;
        int carry = 0;
        #pragma unroll
        for (int base = 0; base < NBLK; base += 32) {
            int idx = base + lane;
            int v = (idx < NBLK) ? bs[idx] : 0;
            int s = v;
            #pragma unroll
            for (int o = 1; o < 32; o <<= 1) {
                int t = __shfl_up_sync(~0u, s, o);
                if (lane >= o) s += t;
            }
            if (idx < NBLK) bs[idx] = carry + s - v;   // exclusive prefix
            carry += __shfl_sync(~0u, s, 31);
        }
    }
    __syncthreads();
    int i = blockIdx.x*blockDim.x + tid;
    if (i < N_NODES) {
        int o = g_off[i] + bs[i >> 10];
        g_off[i] = o;
        g_cursor[i] = o;
        g_deg[i] = 0;                       // restore for next replay
    }
    if (i == 0) g_off[N_NODES] = N_EDGES;   // total degree == edge count
}

__global__ void k_scatter(const int* __restrict__ src, const int* __restrict__ dst) {
    int e = blockIdx.x*blockDim.x + threadIdx.x;
    if (e < N_EDGES) {
        int p = atomicAdd(&g_cursor[dst[e]], 1);
        g_csr[p] = src[e];
    }
}

// ------------------------------------------------ aggregation (CSR gather)
// 16 lanes per node, each lane owns 4 columns (float4). Validated optimum.
// Piggyback (first blocks): zero gsum/gvar/ypool[l&1], emit out(l-1).
__global__ __launch_bounds__(256) void k_agg(const float* __restrict__ x, int use_x,
                                             const float* __restrict__ eps, int l,
                                             const float* __restrict__ pw2p,
                                             const float* __restrict__ pb2p,
                                             float* __restrict__ out, int do_out) {
    unsigned t = blockIdx.x*blockDim.x + threadIdx.x;

    // ---- piggyback: stats-buffer zeroing + previous layer pooled output
    if (t < NGRAPH*HID) {
        g_gsum[t] = 0.f; g_gvar[t] = 0.f;
        g_ypool[l & 1][t] = 0.f;
    }
    if (do_out && t < NGRAPH*TGT) {
        const float* yp = g_ypool[(l-1) & 1];
        int g = t >> 5, c = t & 31;
        float acc = 0.f;
        #pragma unroll 8
        for (int k = 0; k < 64; k++)
            acc = fmaf(yp[g*64 + k], pw2p[k*32 + c], acc);
        float n = g_cnt[g];
        out[g*OUTW + (l-1)*TGT + c] = acc / fmaxf(n, 1.f) + pb2p[c] * fminf(n, 1.f);
    }

    // ---- gather
    unsigned node = t >> 4;
    if (node >= N_NODES) return;
    int j = (int)(t & 15u) << 2;
    const float* __restrict__ f = use_x ? x : g_feat;
    float sc = 1.0f + eps[l];
    float4 acc = *(const float4*)&f[(size_t)node*HID + j];
    acc.x *= sc; acc.y *= sc; acc.z *= sc; acc.w *= sc;
    int b = g_off[node], e = g_off[node+1];
    for (; b + 4 <= e; b += 4) {
        int s0 = g_csr[b], s1 = g_csr[b+1], s2 = g_csr[b+2], s3 = g_csr[b+3];
        float4 v0 = *(const float4*)&f[(size_t)s0*HID + j];
        float4 v1 = *(const float4*)&f[(size_t)s1*HID + j];
        float4 v2 = *(const float4*)&f[(size_t)s2*HID + j];
        float4 v3 = *(const float4*)&f[(size_t)s3*HID + j];
        acc.x += (v0.x + v1.x) + (v2.x + v3.x);
        acc.y += (v0.y + v1.y) + (v2.y + v3.y);
        acc.z += (v0.z + v1.z) + (v2.z + v3.z);
        acc.w += (v0.w + v1.w) + (v2.w + v3.w);
    }
    for (; b < e; b++) {
        int s = g_csr[b];
        float4 v = *(const float4*)&f[(size_t)s*HID + j];
        acc.x += v.x; acc.y += v.y; acc.z += v.z; acc.w += v.w;
    }
    *(float4*)&g_A[(size_t)node*HID + j] = acc;
}

// ============================================================ fused kernel 1
// MLP (2 GEMMs, col-pair x 8-row FFMA2 tile) + GraphNorm stats epilogue
__global__ __launch_bounds__(256) void k_conv(
    const float* __restrict__ w1, const float* __restrict__ b1,
    const float* __restrict__ w2, const float* __restrict__ b2,
    const int*   __restrict__ gid)
{
    __shared__ float W1s[4096];
    __shared__ float W2s[4096];
    __shared__ float As[64*68];
    __shared__ float b1s[64], b2s[64];
    __shared__ int   gids[64];

    const int tid  = threadIdx.x;
    const int row0 = blockIdx.x * 64;

    for (int i = tid; i < 4096; i += 256) { W1s[i] = w1[i]; W2s[i] = w2[i]; }
    if (tid < 64) {
        b1s[tid] = b1[tid]; b2s[tid] = b2[tid];
        int r = row0 + tid;
        gids[tid] = (r < N_NODES) ? gid[r] : 0;
    }
    #pragma unroll
    for (int it = 0; it < 4; it++) {
        int i = it*256 + tid;
        int r = i >> 4, kk = (i & 15) << 2;
        int row = row0 + r;
        float4 v = make_float4(0.f,0.f,0.f,0.f);
        if (row < N_NODES) v = *(const float4*)&g_A[(size_t)row*64 + kk];
        *(float4*)&As[r*68 + kk] = v;
    }
    __syncthreads();

    const int cp = tid & 31;
    const int wr = tid >> 5;
    const float* arow = &As[wr*8*68];

    ull acc[8];
    {
        ull bb = pk2(b1s[2*cp], b1s[2*cp+1]);
        #pragma unroll
        for (int r = 0; r < 8; r++) acc[r] = bb;
    }
    #pragma unroll 4
    for (int k = 0; k < 64; k += 4) {
        ull w0 = *(const ull*)&W1s[(k+0)*64 + 2*cp];
        ull w1v = *(const ull*)&W1s[(k+1)*64 + 2*cp];
        ull w2v = *(const ull*)&W1s[(k+2)*64 + 2*cp];
        ull w3v = *(const ull*)&W1s[(k+3)*64 + 2*cp];
        #pragma unroll
        for (int rr = 0; rr < 8; rr++) {
            float4 a = *(const float4*)&arow[rr*68 + k];
            acc[rr] = ffma2(dup2(a.x), w0,  acc[rr]);
            acc[rr] = ffma2(dup2(a.y), w1v, acc[rr]);
            acc[rr] = ffma2(dup2(a.z), w2v, acc[rr]);
            acc[rr] = ffma2(dup2(a.w), w3v, acc[rr]);
        }
    }
    __syncthreads();
    #pragma unroll
    for (int rr = 0; rr < 8; rr++) {
        float2 h = up2(acc[rr]);
        *(float2*)&As[(wr*8+rr)*68 + 2*cp] =
            make_float2(fmaxf(h.x, 0.f), fmaxf(h.y, 0.f));
    }
    __syncthreads();

    {
        ull bb = pk2(b2s[2*cp], b2s[2*cp+1]);
        #pragma unroll
        for (int r = 0; r < 8; r++) acc[r] = bb;
    }
    #pragma unroll 4
    for (int k = 0; k < 64; k += 4) {
        ull w0 = *(const ull*)&W2s[(k+0)*64 + 2*cp];
        ull w1v = *(const ull*)&W2s[(k+1)*64 + 2*cp];
        ull w2v = *(const ull*)&W2s[(k+2)*64 + 2*cp];
        ull w3v = *(const ull*)&W2s[(k+3)*64 + 2*cp];
        #pragma unroll
        for (int rr = 0; rr < 8; rr++) {
            float4 a = *(const float4*)&arow[rr*68 + k];
            acc[rr] = ffma2(dup2(a.x), w0,  acc[rr]);
            acc[rr] = ffma2(dup2(a.y), w1v, acc[rr]);
            acc[rr] = ffma2(dup2(a.z), w2v, acc[rr]);
            acc[rr] = ffma2(dup2(a.w), w3v, acc[rr]);
        }
    }

    float s0=0.f, s1=0.f, q0=0.f, q1=0.f;
    int cur = gids[wr*8];
    #pragma unroll
    for (int rr = 0; rr < 8; rr++) {
        int row = row0 + wr*8 + rr;
        if (row < N_NODES) {
            float2 h = up2(acc[rr]);
            *(float2*)&g_h[(size_t)row*64 + 2*cp] = h;
            int g = gids[wr*8 + rr];
            if (g != cur) {
                atomicAdd(&g_gsum[cur*64 + 2*cp],   s0);
                atomicAdd(&g_gsum[cur*64 + 2*cp+1], s1);
                atomicAdd(&g_gvar[cur*64 + 2*cp],   q0);
                atomicAdd(&g_gvar[cur*64 + 2*cp+1], q1);
                s0=s1=q0=q1=0.f; cur = g;
            }
            s0 += h.x; s1 += h.y; q0 += h.x*h.x; q1 += h.y*h.y;
        }
    }
    atomicAdd(&g_gsum[cur*64 + 2*cp],   s0);
    atomicAdd(&g_gsum[cur*64 + 2*cp+1], s1);
    atomicAdd(&g_gvar[cur*64 + 2*cp],   q0);
    atomicAdd(&g_gvar[cur*64 + 2*cp+1], q1);
}

// ============================================================ fused kernel 2
// inline GraphNorm coeffs -> affine+relu -> proj GEMM1 -> relu -> y pooling
__global__ __launch_bounds__(256) void k_proj(
    const float* __restrict__ pw1, const float* __restrict__ pb1,
    const float* __restrict__ gns, const float* __restrict__ gnw,
    const float* __restrict__ gnb,
    const int*   __restrict__ gid, int l, int last)
{
    __shared__ float W1s[4096];
    __shared__ float As[64*68];
    __shared__ float b1s[64], gnsS[64], gnwS[64], gnbS[64];
    __shared__ float alS[MAXG*64], beS[MAXG*64];
    __shared__ int   gids[64];

    float* __restrict__ yp = g_ypool[l & 1];

    const int tid  = threadIdx.x;
    const int row0 = blockIdx.x * 64;

    for (int i = tid; i < 4096; i += 256) W1s[i] = pw1[i];
    if (tid < 64) {
        b1s[tid]  = pb1[tid];
        gnsS[tid] = gns[tid];
        gnwS[tid] = gnw[tid];
        gnbS[tid] = gnb[tid];
        int r = row0 + tid;
        gids[tid] = gid[(r < N_NODES) ? r : (N_NODES-1)];
    }
    __syncthreads();

    const int g0  = gids[0];
    const int ngr = gids[63] - g0 + 1;
    const bool fast = (ngr <= MAXG);
    if (fast) {
        for (int i = tid; i < ngr*64; i += 256) {
            int g = g0 + (i >> 6), c = i & 63;
            float n  = fmaxf(g_cnt[g], 1.f);
            float m  = g_gsum[g*64 + c] / n;
            float e2 = g_gvar[g*64 + c] / n;
            float s  = gnsS[c];
            float var = e2 - m*m*s*(2.f - s);
            float sd  = sqrtf(fmaxf(var, 0.f) + 1e-8f);
            float al  = gnwS[c] / sd;
            alS[i] = al;
            beS[i] = gnbS[c] - al*m*s;
        }
    }
    __syncthreads();

    #pragma unroll
    for (int it = 0; it < 4; it++) {
        int i = it*256 + tid;
        int r = i >> 4, kk = (i & 15) << 2;
        int row = row0 + r;
        float4 v = make_float4(0.f,0.f,0.f,0.f);
        if (row < N_NODES) {
            int g = gids[r];
            float4 h = *(const float4*)&g_h[(size_t)row*64 + kk];
            float4 al, be;
            if (fast) {
                int o = (g - g0)*64 + kk;
                al = *(const float4*)&alS[o];
                be = *(const float4*)&beS[o];
            } else {
                float n = fmaxf(g_cnt[g], 1.f);
                #pragma unroll
                for (int q = 0; q < 4; q++) {
                    int c = kk + q;
                    float m  = g_gsum[g*64 + c] / n;
                    float e2 = g_gvar[g*64 + c] / n;
                    float s  = gnsS[c];
                    float var = e2 - m*m*s*(2.f - s);
                    float sd  = sqrtf(fmaxf(var, 0.f) + 1e-8f);
                    float a   = gnwS[c] / sd;
                    float bcoef = gnbS[c] - a*m*s;
                    ((float*)&al)[q] = a;
                    ((float*)&be)[q] = bcoef;
                }
            }
            v.x = fmaxf(fmaf(al.x, h.x, be.x), 0.f);
            v.y = fmaxf(fmaf(al.y, h.y, be.y), 0.f);
            v.z = fmaxf(fmaf(al.z, h.z, be.z), 0.f);
            v.w = fmaxf(fmaf(al.w, h.w, be.w), 0.f);
            if (!last) *(float4*)&g_feat[(size_t)row*64 + kk] = v;
        }
        *(float4*)&As[r*68 + kk] = v;
    }
    __syncthreads();

    const int cp = tid & 31;
    const int wr = tid >> 5;
    const float* arow = &As[wr*8*68];
    ull acc[8];
    {
        ull bb = pk2(b1s[2*cp], b1s[2*cp+1]);
        #pragma unroll
        for (int r = 0; r < 8; r++) acc[r] = bb;
    }
    #pragma unroll 4
    for (int k = 0; k < 64; k += 4) {
        ull w0 = *(const ull*)&W1s[(k+0)*64 + 2*cp];
        ull w1v = *(const ull*)&W1s[(k+1)*64 + 2*cp];
        ull w2v = *(const ull*)&W1s[(k+2)*64 + 2*cp];
        ull w3v = *(const ull*)&W1s[(k+3)*64 + 2*cp];
        #pragma unroll
        for (int rr = 0; rr < 8; rr++) {
            float4 a = *(const float4*)&arow[rr*68 + k];
            acc[rr] = ffma2(dup2(a.x), w0,  acc[rr]);
            acc[rr] = ffma2(dup2(a.y), w1v, acc[rr]);
            acc[rr] = ffma2(dup2(a.z), w2v, acc[rr]);
            acc[rr] = ffma2(dup2(a.w), w3v, acc[rr]);
        }
    }

    float s0 = 0.f, s1 = 0.f;
    int cur = gids[wr*8];
    #pragma unroll
    for (int rr = 0; rr < 8; rr++) {
        int row = row0 + wr*8 + rr;
        if (row < N_NODES) {
            float2 p = up2(acc[rr]);
            float y0 = fmaxf(p.x, 0.f), y1 = fmaxf(p.y, 0.f);
            int g = gids[wr*8 + rr];
            if (g != cur) {
                atomicAdd(&yp[cur*64 + 2*cp],   s0);
                atomicAdd(&yp[cur*64 + 2*cp+1], s1);
                s0 = 0.f; s1 = 0.f; cur = g;
            }
            s0 += y0; s1 += y1;
        }
    }
    atomicAdd(&yp[cur*64 + 2*cp],   s0);
    atomicAdd(&yp[cur*64 + 2*cp+1], s1);
}

// final-layer pooled output; also restores g_cnt = 0 for next replay.
// Each warp covers exactly one graph (NGRAPH*TGT is warp-aligned): lane 0
// atomically exchanges the count with 0 and broadcasts it.
__global__ void k_out(const float* __restrict__ pw2, const float* __restrict__ pb2,
                      float* __restrict__ out, int l) {
    int i = blockIdx.x*blockDim.x + threadIdx.x;
    if (i >= NGRAPH*TGT) return;
    const float* yp = g_ypool[l & 1];
    int g = i >> 5, c = i & 31;
    float n = 0.f;
    if (c == 0) n = atomicExch(&g_cnt[g], 0.f);
    n = __shfl_sync(~0u, n, 0);
    float acc = 0.f;
    #pragma unroll 8
    for (int k = 0; k < 64; k++)
        acc = fmaf(yp[g*64 + k], pw2[k*32 + c], acc);
    out[g*OUTW + l*TGT + c] = acc / fmaxf(n, 1.f) + pb2[c] * fminf(n, 1.f);
}

// ---------------------------------------------------------------- launcher

extern "C" void kernel_launch(void* const* d_in, const int* in_sizes, int n_in,
                              void* d_out, int out_size) {
    const float* x   = (const float*)d_in[0];
    const int*   src = (const int*)  d_in[1];
    const int*   dst = (const int*)  d_in[2];
    const int*   gid = (const int*)  d_in[3];
    const float* eps = (const float*)d_in[4];
    const float* cw1 = (const float*)d_in[5];
    const float* cb1 = (const float*)d_in[6];
    const float* cw2 = (const float*)d_in[7];
    const float* cb2 = (const float*)d_in[8];
    const float* gnw = (const float*)d_in[9];
    const float* gnb = (const float*)d_in[10];
    const float* gns = (const float*)d_in[11];
    const float* pw1 = (const float*)d_in[12];
    const float* pb1 = (const float*)d_in[13];
    const float* pw2 = (const float*)d_in[14];
    const float* pb2 = (const float*)d_in[15];
    float* out = (float*)d_out;

    const int EB = (N_EDGES + 255)/256;
    const int NB = (N_NODES + 255)/256;

    k_histcnt<<<EB, 256>>>(dst, gid);
    k_scan1<<<NBLK, SCAN_B>>>();
    k_scan3<<<NB, 256>>>();
    k_scatter<<<EB, 256>>>(src, dst);

    const int GB = (N_NODES + 63)/64;
    const int AB = (N_NODES*16 + 255)/256;

    for (int l = 0; l < NLAY; l++) {
        int use_x = (l == 0) ? 1 : 0;
        int last  = (l == NLAY-1) ? 1 : 0;
        k_agg<<<AB, 256>>>(x, use_x, eps, l,
                           pw2 + (l-1)*2048, pb2 + (l-1)*32, out, l > 0);
        k_conv<<<GB, 256>>>(cw1 + l*4096, cb1 + l*64,
                            cw2 + l*4096, cb2 + l*64, gid);
        k_proj<<<GB, 256>>>(pw1 + l*4096, pb1 + l*64,
                            gns + l*64, gnw + l*64, gnb + l*64,
                            gid, l, last);
    }
    k_out<<<(NGRAPH*TGT + 255)/256, 256>>>(pw2 + (NLAY-1)*2048,
                                           pb2 + (NLAY-1)*32, out, NLAY-1);
}

// round 17
// speedup vs baseline: 1.1006x; 1.0084x over previous
#include <cuda_runtime.h>
#include <stdint.h>

#define N_NODES 100000
#define N_EDGES 1200000
#define HID     64
#define TGT     32
#define NLAY    3
#define NGRAPH  500
#define OUTW    (NLAY*TGT)   // 96
#define SCAN_B  1024
#define NBLK    ((N_NODES + SCAN_B - 1)/SCAN_B)   // 98
#define MAXG    8            // fast-path max distinct graphs per 64-row block

typedef unsigned long long ull;

// ---------------------------------------------------------------- scratch
// __device__ globals are zero-initialized at module load; pipeline is
// self-restoring (scan3 re-zeros g_deg, k_out re-zeros g_cnt).
static __device__ float g_feat[N_NODES*HID];
static __device__ float g_A   [N_NODES*HID];
static __device__ float g_h   [N_NODES*HID];
static __device__ float g_gsum [NGRAPH*HID];
static __device__ float g_gvar [NGRAPH*HID];
static __device__ float g_ypool[2][NGRAPH*HID];   // double-buffered per layer
static __device__ float g_cnt  [NGRAPH];
static __device__ int   g_deg  [N_NODES];
static __device__ int   g_off  [N_NODES+1];
static __device__ int   g_cursor[N_NODES];
static __device__ int   g_csr  [N_EDGES];
static __device__ int   g_bsum [NBLK];

// ---------------------------------------------------------------- f32x2
__device__ __forceinline__ ull dup2(float x) {
    ull r; asm("mov.b64 %0, {%1, %1};" : "=l"(r) : "f"(x)); return r;
}
__device__ __forceinline__ ull pk2(float x, float y) {
    ull r; asm("mov.b64 %0, {%1, %2};" : "=l"(r) : "f"(x), "f"(y)); return r;
}
__device__ __forceinline__ float2 up2(ull v) {
    float lo, hi; asm("mov.b64 {%0, %1}, %2;" : "=f"(lo), "=f"(hi) : "l"(v));
    return make_float2(lo, hi);
}
__device__ __forceinline__ ull ffma2(ull a, ull b, ull c) {
    ull d; asm("fma.rn.f32x2 %0, %1, %2, %3;" : "=l"(d) : "l"(a), "l"(b), "l"(c));
    return d;
}

// ---------------------------------------------------------------- setup

// degree histogram + per-graph node counts, 4 elements per thread (int4)
__global__ void k_histcnt(const int* __restrict__ dst, const int* __restrict__ gid) {
    int t = blockIdx.x*blockDim.x + threadIdx.x;
    int e4 = t * 4;
    if (e4 < N_EDGES) {   // N_EDGES % 4 == 0
        int4 d = *(const int4*)&dst[e4];
        atomicAdd(&g_deg[d.x], 1);
        atomicAdd(&g_deg[d.y], 1);
        atomicAdd(&g_deg[d.z], 1);
        atomicAdd(&g_deg[d.w], 1);
    }
    if (e4 < N_NODES) {   // N_NODES % 4 == 0
        int4 g = *(const int4*)&gid[e4];
        atomicAdd(&g_cnt[g.x], 1.0f);
        atomicAdd(&g_cnt[g.y], 1.0f);
        atomicAdd(&g_cnt[g.z], 1.0f);
        atomicAdd(&g_cnt[g.w], 1.0f);
    }
}

// ---------------- scan of degrees (block-local, then fixup)

__global__ __launch_bounds__(SCAN_B) void k_scan1() {
    __shared__ int wsum[32];
    int i = blockIdx.x*SCAN_B + threadIdx.x;
    int lane = threadIdx.x & 31, wid = threadIdx.x >> 5;
    int v = (i < N_NODES) ? g_deg[i] : 0;
    int s = v;
    #pragma unroll
    for (int o = 1; o < 32; o <<= 1) {
        int t = __shfl_up_sync(~0u, s, o);
        if (lane >= o) s += t;
    }
    if (lane == 31) wsum[wid] = s;
    __syncthreads();
    if (wid == 0) {
        int ws = wsum[lane];
        #pragma unroll
        for (int o = 1; o < 32; o <<= 1) {
            int t = __shfl_up_sync(~0u, ws, o);
            if (lane >= o) ws += t;
        }
        wsum[lane] = ws;
    }
    __syncthreads();
    int excl = s - v + ((wid > 0) ? wsum[wid-1] : 0);
    if (i < N_NODES) g_off[i] = excl;
    if (threadIdx.x == SCAN_B-1) g_bsum[blockIdx.x] = wsum[31];
}

// fixup: warp-scan block totals into exclusive prefix (smem), add, cursors.
// Also re-zeros g_deg for the next replay (last reader was k_scan1).
__global__ void k_scan3() {
    __shared__ int bs[NBLK];
    int tid = threadIdx.x;
    if (tid < NBLK) bs[tid] = g_bsum[tid];
    __syncthreads();
    if (tid < 32) {
        int lane = tid;
        int carry = 0;
        #pragma unroll
        for (int base = 0; base < NBLK; base += 32) {
            int idx = base + lane;
            int v = (idx < NBLK) ? bs[idx] : 0;
            int s = v;
            #pragma unroll
            for (int o = 1; o < 32; o <<= 1) {
                int t = __shfl_up_sync(~0u, s, o);
                if (lane >= o) s += t;
            }
            if (idx < NBLK) bs[idx] = carry + s - v;   // exclusive prefix
            carry += __shfl_sync(~0u, s, 31);
        }
    }
    __syncthreads();
    int i = blockIdx.x*blockDim.x + tid;
    if (i < N_NODES) {
        int o = g_off[i] + bs[i >> 10];
        g_off[i] = o;
        g_cursor[i] = o;
        g_deg[i] = 0;                       // restore for next replay
    }
    if (i == 0) g_off[N_NODES] = N_EDGES;
}

// CSR scatter, 4 edges per thread (int4 loads -> 4 in-flight atomics)
__global__ void k_scatter(const int* __restrict__ src, const int* __restrict__ dst) {
    int t = blockIdx.x*blockDim.x + threadIdx.x;
    int e4 = t * 4;
    if (e4 >= N_EDGES) return;
    int4 s = *(const int4*)&src[e4];
    int4 d = *(const int4*)&dst[e4];
    int p0 = atomicAdd(&g_cursor[d.x], 1);
    int p1 = atomicAdd(&g_cursor[d.y], 1);
    int p2 = atomicAdd(&g_cursor[d.z], 1);
    int p3 = atomicAdd(&g_cursor[d.w], 1);
    g_csr[p0] = s.x;
    g_csr[p1] = s.y;
    g_csr[p2] = s.z;
    g_csr[p3] = s.w;
}

// ------------------------------------------------ aggregation (CSR gather)
// 16 lanes per node, each lane owns 4 columns (float4). Validated optimum.
// Piggyback (first blocks): zero gsum/gvar/ypool[l&1], emit out(l-1).
__global__ __launch_bounds__(256) void k_agg(const float* __restrict__ x, int use_x,
                                             const float* __restrict__ eps, int l,
                                             const float* __restrict__ pw2p,
                                             const float* __restrict__ pb2p,
                                             float* __restrict__ out, int do_out) {
    unsigned t = blockIdx.x*blockDim.x + threadIdx.x;

    if (t < NGRAPH*HID) {
        g_gsum[t] = 0.f; g_gvar[t] = 0.f;
        g_ypool[l & 1][t] = 0.f;
    }
    if (do_out && t < NGRAPH*TGT) {
        const float* yp = g_ypool[(l-1) & 1];
        int g = t >> 5, c = t & 31;
        float acc = 0.f;
        #pragma unroll 8
        for (int k = 0; k < 64; k++)
            acc = fmaf(yp[g*64 + k], pw2p[k*32 + c], acc);
        float n = g_cnt[g];
        out[g*OUTW + (l-1)*TGT + c] = acc / fmaxf(n, 1.f) + pb2p[c] * fminf(n, 1.f);
    }

    unsigned node = t >> 4;
    if (node >= N_NODES) return;
    int j = (int)(t & 15u) << 2;
    const float* __restrict__ f = use_x ? x : g_feat;
    float sc = 1.0f + eps[l];
    float4 acc = *(const float4*)&f[(size_t)node*HID + j];
    acc.x *= sc; acc.y *= sc; acc.z *= sc; acc.w *= sc;
    int b = g_off[node], e = g_off[node+1];
    for (; b + 4 <= e; b += 4) {
        int s0 = g_csr[b], s1 = g_csr[b+1], s2 = g_csr[b+2], s3 = g_csr[b+3];
        float4 v0 = *(const float4*)&f[(size_t)s0*HID + j];
        float4 v1 = *(const float4*)&f[(size_t)s1*HID + j];
        float4 v2 = *(const float4*)&f[(size_t)s2*HID + j];
        float4 v3 = *(const float4*)&f[(size_t)s3*HID + j];
        acc.x += (v0.x + v1.x) + (v2.x + v3.x);
        acc.y += (v0.y + v1.y) + (v2.y + v3.y);
        acc.z += (v0.z + v1.z) + (v2.z + v3.z);
        acc.w += (v0.w + v1.w) + (v2.w + v3.w);
    }
    for (; b < e; b++) {
        int s = g_csr[b];
        float4 v = *(const float4*)&f[(size_t)s*HID + j];
        acc.x += v.x; acc.y += v.y; acc.z += v.z; acc.w += v.w;
    }
    *(float4*)&g_A[(size_t)node*HID + j] = acc;
}

// ============================================================ fused kernel 1
// MLP (2 GEMMs, col-pair x 8-row FFMA2 tile) + GraphNorm stats epilogue
__global__ __launch_bounds__(256) void k_conv(
    const float* __restrict__ w1, const float* __restrict__ b1,
    const float* __restrict__ w2, const float* __restrict__ b2,
    const int*   __restrict__ gid)
{
    __shared__ float W1s[4096];
    __shared__ float W2s[4096];
    __shared__ float As[64*68];
    __shared__ float b1s[64], b2s[64];
    __shared__ int   gids[64];

    const int tid  = threadIdx.x;
    const int row0 = blockIdx.x * 64;

    for (int i = tid; i < 4096; i += 256) { W1s[i] = w1[i]; W2s[i] = w2[i]; }
    if (tid < 64) {
        b1s[tid] = b1[tid]; b2s[tid] = b2[tid];
        int r = row0 + tid;
        gids[tid] = (r < N_NODES) ? gid[r] : 0;
    }
    #pragma unroll
    for (int it = 0; it < 4; it++) {
        int i = it*256 + tid;
        int r = i >> 4, kk = (i & 15) << 2;
        int row = row0 + r;
        float4 v = make_float4(0.f,0.f,0.f,0.f);
        if (row < N_NODES) v = *(const float4*)&g_A[(size_t)row*64 + kk];
        *(float4*)&As[r*68 + kk] = v;
    }
    __syncthreads();

    const int cp = tid & 31;
    const int wr = tid >> 5;
    const float* arow = &As[wr*8*68];

    ull acc[8];
    {
        ull bb = pk2(b1s[2*cp], b1s[2*cp+1]);
        #pragma unroll
        for (int r = 0; r < 8; r++) acc[r] = bb;
    }
    #pragma unroll 4
    for (int k = 0; k < 64; k += 4) {
        ull w0 = *(const ull*)&W1s[(k+0)*64 + 2*cp];
        ull w1v = *(const ull*)&W1s[(k+1)*64 + 2*cp];
        ull w2v = *(const ull*)&W1s[(k+2)*64 + 2*cp];
        ull w3v = *(const ull*)&W1s[(k+3)*64 + 2*cp];
        #pragma unroll
        for (int rr = 0; rr < 8; rr++) {
            float4 a = *(const float4*)&arow[rr*68 + k];
            acc[rr] = ffma2(dup2(a.x), w0,  acc[rr]);
            acc[rr] = ffma2(dup2(a.y), w1v, acc[rr]);
            acc[rr] = ffma2(dup2(a.z), w2v, acc[rr]);
            acc[rr] = ffma2(dup2(a.w), w3v, acc[rr]);
        }
    }
    __syncthreads();
    #pragma unroll
    for (int rr = 0; rr < 8; rr++) {
        float2 h = up2(acc[rr]);
        *(float2*)&As[(wr*8+rr)*68 + 2*cp] =
            make_float2(fmaxf(h.x, 0.f), fmaxf(h.y, 0.f));
    }
    __syncthreads();

    {
        ull bb = pk2(b2s[2*cp], b2s[2*cp+1]);
        #pragma unroll
        for (int r = 0; r < 8; r++) acc[r] = bb;
    }
    #pragma unroll 4
    for (int k = 0; k < 64; k += 4) {
        ull w0 = *(const ull*)&W2s[(k+0)*64 + 2*cp];
        ull w1v = *(const ull*)&W2s[(k+1)*64 + 2*cp];
        ull w2v = *(const ull*)&W2s[(k+2)*64 + 2*cp];
        ull w3v = *(const ull*)&W2s[(k+3)*64 + 2*cp];
        #pragma unroll
        for (int rr = 0; rr < 8; rr++) {
            float4 a = *(const float4*)&arow[rr*68 + k];
            acc[rr] = ffma2(dup2(a.x), w0,  acc[rr]);
            acc[rr] = ffma2(dup2(a.y), w1v, acc[rr]);
            acc[rr] = ffma2(dup2(a.z), w2v, acc[rr]);
            acc[rr] = ffma2(dup2(a.w), w3v, acc[rr]);
        }
    }

    float s0=0.f, s1=0.f, q0=0.f, q1=0.f;
    int cur = gids[wr*8];
    #pragma unroll
    for (int rr = 0; rr < 8; rr++) {
        int row = row0 + wr*8 + rr;
        if (row < N_NODES) {
            float2 h = up2(acc[rr]);
            *(float2*)&g_h[(size_t)row*64 + 2*cp] = h;
            int g = gids[wr*8 + rr];
            if (g != cur) {
                atomicAdd(&g_gsum[cur*64 + 2*cp],   s0);
                atomicAdd(&g_gsum[cur*64 + 2*cp+1], s1);
                atomicAdd(&g_gvar[cur*64 + 2*cp],   q0);
                atomicAdd(&g_gvar[cur*64 + 2*cp+1], q1);
                s0=s1=q0=q1=0.f; cur = g;
            }
            s0 += h.x; s1 += h.y; q0 += h.x*h.x; q1 += h.y*h.y;
        }
    }
    atomicAdd(&g_gsum[cur*64 + 2*cp],   s0);
    atomicAdd(&g_gsum[cur*64 + 2*cp+1], s1);
    atomicAdd(&g_gvar[cur*64 + 2*cp],   q0);
    atomicAdd(&g_gvar[cur*64 + 2*cp+1], q1);
}

// ============================================================ fused kernel 2
// inline GraphNorm coeffs -> affine+relu -> proj GEMM1 -> relu -> y pooling
__global__ __launch_bounds__(256) void k_proj(
    const float* __restrict__ pw1, const float* __restrict__ pb1,
    const float* __restrict__ gns, const float* __restrict__ gnw,
    const float* __restrict__ gnb,
    const int*   __restrict__ gid, int l, int last)
{
    __shared__ float W1s[4096];
    __shared__ float As[64*68];
    __shared__ float b1s[64], gnsS[64], gnwS[64], gnbS[64];
    __shared__ float alS[MAXG*64], beS[MAXG*64];
    __shared__ int   gids[64];

    float* __restrict__ yp = g_ypool[l & 1];

    const int tid  = threadIdx.x;
    const int row0 = blockIdx.x * 64;

    for (int i = tid; i < 4096; i += 256) W1s[i] = pw1[i];
    if (tid < 64) {
        b1s[tid]  = pb1[tid];
        gnsS[tid] = gns[tid];
        gnwS[tid] = gnw[tid];
        gnbS[tid] = gnb[tid];
        int r = row0 + tid;
        gids[tid] = gid[(r < N_NODES) ? r : (N_NODES-1)];
    }
    __syncthreads();

    const int g0  = gids[0];
    const int ngr = gids[63] - g0 + 1;
    const bool fast = (ngr <= MAXG);
    if (fast) {
        for (int i = tid; i < ngr*64; i += 256) {
            int g = g0 + (i >> 6), c = i & 63;
            float n  = fmaxf(g_cnt[g], 1.f);
            float m  = g_gsum[g*64 + c] / n;
            float e2 = g_gvar[g*64 + c] / n;
            float s  = gnsS[c];
            float var = e2 - m*m*s*(2.f - s);
            float sd  = sqrtf(fmaxf(var, 0.f) + 1e-8f);
            float al  = gnwS[c] / sd;
            alS[i] = al;
            beS[i] = gnbS[c] - al*m*s;
        }
    }
    __syncthreads();

    #pragma unroll
    for (int it = 0; it < 4; it++) {
        int i = it*256 + tid;
        int r = i >> 4, kk = (i & 15) << 2;
        int row = row0 + r;
        float4 v = make_float4(0.f,0.f,0.f,0.f);
        if (row < N_NODES) {
            int g = gids[r];
            float4 h = *(const float4*)&g_h[(size_t)row*64 + kk];
            float4 al, be;
            if (fast) {
                int o = (g - g0)*64 + kk;
                al = *(const float4*)&alS[o];
                be = *(const float4*)&beS[o];
            } else {
                float n = fmaxf(g_cnt[g], 1.f);
                #pragma unroll
                for (int q = 0; q < 4; q++) {
                    int c = kk + q;
                    float m  = g_gsum[g*64 + c] / n;
                    float e2 = g_gvar[g*64 + c] / n;
                    float s  = gnsS[c];
                    float var = e2 - m*m*s*(2.f - s);
                    float sd  = sqrtf(fmaxf(var, 0.f) + 1e-8f);
                    float a   = gnwS[c] / sd;
                    float bcoef = gnbS[c] - a*m*s;
                    ((float*)&al)[q] = a;
                    ((float*)&be)[q] = bcoef;
                }
            }
            v.x = fmaxf(fmaf(al.x, h.x, be.x), 0.f);
            v.y = fmaxf(fmaf(al.y, h.y, be.y), 0.f);
            v.z = fmaxf(fmaf(al.z, h.z, be.z), 0.f);
            v.w = fmaxf(fmaf(al.w, h.w, be.w), 0.f);
            if (!last) *(float4*)&g_feat[(size_t)row*64 + kk] = v;
        }
        *(float4*)&As[r*68 + kk] = v;
    }
    __syncthreads();

    const int cp = tid & 31;
    const int wr = tid >> 5;
    const float* arow = &As[wr*8*68];
    ull acc[8];
    {
        ull bb = pk2(b1s[2*cp], b1s[2*cp+1]);
        #pragma unroll
        for (int r = 0; r < 8; r++) acc[r] = bb;
    }
    #pragma unroll 4
    for (int k = 0; k < 64; k += 4) {
        ull w0 = *(const ull*)&W1s[(k+0)*64 + 2*cp];
        ull w1v = *(const ull*)&W1s[(k+1)*64 + 2*cp];
        ull w2v = *(const ull*)&W1s[(k+2)*64 + 2*cp];
        ull w3v = *(const ull*)&W1s[(k+3)*64 + 2*cp];
        #pragma unroll
        for (int rr = 0; rr < 8; rr++) {
            float4 a = *(const float4*)&arow[rr*68 + k];
            acc[rr] = ffma2(dup2(a.x), w0,  acc[rr]);
            acc[rr] = ffma2(dup2(a.y), w1v, acc[rr]);
            acc[rr] = ffma2(dup2(a.z), w2v, acc[rr]);
            acc[rr] = ffma2(dup2(a.w), w3v, acc[rr]);
        }
    }

    float s0 = 0.f, s1 = 0.f;
    int cur = gids[wr*8];
    #pragma unroll
    for (int rr = 0; rr < 8; rr++) {
        int row = row0 + wr*8 + rr;
        if (row < N_NODES) {
            float2 p = up2(acc[rr]);
            float y0 = fmaxf(p.x, 0.f), y1 = fmaxf(p.y, 0.f);
            int g = gids[wr*8 + rr];
            if (g != cur) {
                atomicAdd(&yp[cur*64 + 2*cp],   s0);
                atomicAdd(&yp[cur*64 + 2*cp+1], s1);
                s0 = 0.f; s1 = 0.f; cur = g;
            }
            s0 += y0; s1 += y1;
        }
    }
    atomicAdd(&yp[cur*64 + 2*cp],   s0);
    atomicAdd(&yp[cur*64 + 2*cp+1], s1);
}

// final-layer pooled output; restores g_cnt = 0 for next replay.
__global__ void k_out(const float* __restrict__ pw2, const float* __restrict__ pb2,
                      float* __restrict__ out, int l) {
    int i = blockIdx.x*blockDim.x + threadIdx.x;
    if (i >= NGRAPH*TGT) return;
    const float* yp = g_ypool[l & 1];
    int g = i >> 5, c = i & 31;
    float n = 0.f;
    if (c == 0) n = atomicExch(&g_cnt[g], 0.f);
    n = __shfl_sync(~0u, n, 0);
    float acc = 0.f;
    #pragma unroll 8
    for (int k = 0; k < 64; k++)
        acc = fmaf(yp[g*64 + k], pw2[k*32 + c], acc);
    out[g*OUTW + l*TGT + c] = acc / fmaxf(n, 1.f) + pb2[c] * fminf(n, 1.f);
}

// ---------------------------------------------------------------- launcher

extern "C" void kernel_launch(void* const* d_in, const int* in_sizes, int n_in,
                              void* d_out, int out_size) {
    const float* x   = (const float*)d_in[0];
    const int*   src = (const int*)  d_in[1];
    const int*   dst = (const int*)  d_in[2];
    const int*   gid = (const int*)  d_in[3];
    const float* eps = (const float*)d_in[4];
    const float* cw1 = (const float*)d_in[5];
    const float* cb1 = (const float*)d_in[6];
    const float* cw2 = (const float*)d_in[7];
    const float* cb2 = (const float*)d_in[8];
    const float* gnw = (const float*)d_in[9];
    const float* gnb = (const float*)d_in[10];
    const float* gns = (const float*)d_in[11];
    const float* pw1 = (const float*)d_in[12];
    const float* pb1 = (const float*)d_in[13];
    const float* pw2 = (const float*)d_in[14];
    const float* pb2 = (const float*)d_in[15];
    float* out = (float*)d_out;

    const int E4B = (N_EDGES/4 + 255)/256;
    const int NB  = (N_NODES + 255)/256;

    k_histcnt<<<E4B, 256>>>(dst, gid);
    k_scan1<<<NBLK, SCAN_B>>>();
    k_scan3<<<NB, 256>>>();
    k_scatter<<<E4B, 256>>>(src, dst);

    const int GB = (N_NODES + 63)/64;
    const int AB = (N_NODES*16 + 255)/256;

    for (int l = 0; l < NLAY; l++) {
        int use_x = (l == 0) ? 1 : 0;
        int last  = (l == NLAY-1) ? 1 : 0;
        k_agg<<<AB, 256>>>(x, use_x, eps, l,
                           pw2 + (l-1)*2048, pb2 + (l-1)*32, out, l > 0);
        k_conv<<<GB, 256>>>(cw1 + l*4096, cb1 + l*64,
                            cw2 + l*4096, cb2 + l*64, gid);
        k_proj<<<GB, 256>>>(pw1 + l*4096, pb1 + l*64,
                            gns + l*64, gnw + l*64, gnb + l*64,
                            gid, l, last);
    }
    k_out<<<(NGRAPH*TGT + 255)/256, 256>>>(pw2 + (NLAY-1)*2048,
                                           pb2 + (NLAY-1)*32, out, NLAY-1);
}